// round 1
// baseline (speedup 1.0000x reference)
#include <cuda_runtime.h>
#include <cstdint>

// Problem constants (fixed by the reference setup_inputs)
#define BATCH 2
#define SEQ   2048
#define DMODEL 1024
#define NHEAD 16
#define DK    64
#define MROWS (BATCH * SEQ)   // 4096

// Scratch: Q,K,V in [B,H,S,DK], O in [B,S,D]
__device__ float g_Q[BATCH * NHEAD * SEQ * DK];
__device__ float g_K[BATCH * NHEAD * SEQ * DK];
__device__ float g_V[BATCH * NHEAD * SEQ * DK];
__device__ float g_O[BATCH * SEQ * DMODEL];

// ---------------------------------------------------------------------------
// GEMM: C[M,N] = A[M,K] @ W[N,K]^T  (both row-major, K contiguous -> NT gemm)
// mode 0/1/2: A = input tensor, output head-split into g_Q/g_K/g_V
// mode 3:     A = g_O, output flat into outFlat with bias
// M=4096, N=1024, K=1024 fixed.
// Tile 128x128x16, 256 threads, 8x8 microtile (split 4+4 for conflict-free LDS)
// ---------------------------------------------------------------------------
#define GBK 16
#define GPAD 132  // padded row stride in smem

__global__ __launch_bounds__(256, 2) void gemm_kernel(
    const float* __restrict__ A, const float* __restrict__ W,
    const float* __restrict__ bias, float* __restrict__ outFlat, int mode)
{
    __shared__ float As[GBK][GPAD];
    __shared__ float Ws[GBK][GPAD];

    const float* Ap = (mode == 3) ? g_O : A;

    const int tid = threadIdx.x;
    const int tx = tid & 15;
    const int ty = tid >> 4;
    const int m0 = blockIdx.y << 7;
    const int n0 = blockIdx.x << 7;

    float acc[8][8];
#pragma unroll
    for (int i = 0; i < 8; i++)
#pragma unroll
        for (int j = 0; j < 8; j++) acc[i][j] = 0.f;

    for (int k0 = 0; k0 < DMODEL; k0 += GBK) {
#pragma unroll
        for (int it = 0; it < 2; it++) {
            int f = tid + (it << 8);          // 0..511
            int r = f >> 2;                   // 0..127
            int c4 = (f & 3) << 2;            // 0,4,8,12
            float4 va = *(const float4*)&Ap[(m0 + r) * DMODEL + k0 + c4];
            As[c4 + 0][r] = va.x; As[c4 + 1][r] = va.y;
            As[c4 + 2][r] = va.z; As[c4 + 3][r] = va.w;
            float4 vw = *(const float4*)&W[(n0 + r) * DMODEL + k0 + c4];
            Ws[c4 + 0][r] = vw.x; Ws[c4 + 1][r] = vw.y;
            Ws[c4 + 2][r] = vw.z; Ws[c4 + 3][r] = vw.w;
        }
        __syncthreads();

#pragma unroll
        for (int kk = 0; kk < GBK; kk++) {
            float a[8], b[8];
            float4 a0 = *(const float4*)&As[kk][ty << 2];
            float4 a1 = *(const float4*)&As[kk][64 + (ty << 2)];
            float4 b0 = *(const float4*)&Ws[kk][tx << 2];
            float4 b1 = *(const float4*)&Ws[kk][64 + (tx << 2)];
            a[0] = a0.x; a[1] = a0.y; a[2] = a0.z; a[3] = a0.w;
            a[4] = a1.x; a[5] = a1.y; a[6] = a1.z; a[7] = a1.w;
            b[0] = b0.x; b[1] = b0.y; b[2] = b0.z; b[3] = b0.w;
            b[4] = b1.x; b[5] = b1.y; b[6] = b1.z; b[7] = b1.w;
#pragma unroll
            for (int i = 0; i < 8; i++)
#pragma unroll
                for (int j = 0; j < 8; j++) acc[i][j] += a[i] * b[j];
        }
        __syncthreads();
    }

    if (mode == 3) {
#pragma unroll
        for (int i = 0; i < 8; i++) {
            int r = (i < 4) ? ((ty << 2) + i) : (64 + (ty << 2) + i - 4);
            int m = m0 + r;
#pragma unroll
            for (int jg = 0; jg < 2; jg++) {
                int c = (jg << 6) + (tx << 2);
                int n = n0 + c;
                float4 o;
                o.x = acc[i][(jg << 2) + 0] + bias[n + 0];
                o.y = acc[i][(jg << 2) + 1] + bias[n + 1];
                o.z = acc[i][(jg << 2) + 2] + bias[n + 2];
                o.w = acc[i][(jg << 2) + 3] + bias[n + 3];
                *(float4*)&outFlat[m * DMODEL + n] = o;
            }
        }
    } else {
        float* outp = (mode == 0) ? g_Q : ((mode == 1) ? g_K : g_V);
#pragma unroll
        for (int i = 0; i < 8; i++) {
            int r = (i < 4) ? ((ty << 2) + i) : (64 + (ty << 2) + i - 4);
            int m = m0 + r;
            int bb = m >> 11;          // / SEQ
            int s  = m & 2047;
#pragma unroll
            for (int jg = 0; jg < 2; jg++) {
                int c = (jg << 6) + (tx << 2);
                int n = n0 + c;
                int h = n >> 6;
                int d = n & 63;
                float4 o;
                o.x = acc[i][(jg << 2) + 0];
                o.y = acc[i][(jg << 2) + 1];
                o.z = acc[i][(jg << 2) + 2];
                o.w = acc[i][(jg << 2) + 3];
                *(float4*)&outp[(((bb << 4) + h) * SEQ + s) * DK + d] = o;
            }
        }
    }
}

// ---------------------------------------------------------------------------
// Flash attention (fp32), causal + boolean mask.
// Grid: (S/64 q-tiles, B*H). 256 threads; 4 threads per query row (a quad).
// smem: Qs/Ks/Vs/Ps 64x68 each (padded), dynamic (69632 B).
// ---------------------------------------------------------------------------
#define APAD 68

__global__ __launch_bounds__(256) void attn_kernel(
    const unsigned char* __restrict__ mask, const int* __restrict__ is_causal_p)
{
    extern __shared__ float sm[];
    typedef float Row[APAD];
    Row* Qs = (Row*)sm;
    Row* Ks = Qs + 64;
    Row* Vs = Ks + 64;
    Row* Ps = Vs + 64;

    const int bh = blockIdx.y;           // 0..31
    const int qt = blockIdx.x;           // 0..31
    const int b  = bh >> 4;              // / NHEAD
    const int h  = bh & 15;
    const int causal = is_causal_p[0];
    const int q0 = qt << 6;
    const int tid = threadIdx.x;

    const float* Qg = g_Q + ((size_t)bh * SEQ + q0) * DK;
    const float* Kg = g_K + (size_t)bh * SEQ * DK;
    const float* Vg = g_V + (size_t)bh * SEQ * DK;

    // Load Q tile (64 x 64)
#pragma unroll
    for (int it = 0; it < 4; it++) {
        int f = tid + (it << 8);
        int r = f >> 4;
        int c4 = (f & 15) << 2;
        *(float4*)&Qs[r][c4] = *(const float4*)&Qg[r * DK + c4];
    }

    const int row = tid >> 2;            // 0..63
    const int q   = tid & 3;             // quad lane
    const int gr  = q0 + row;            // global query row

    float m_i = -1e30f, l_i = 0.f;
    float o[16];
#pragma unroll
    for (int j = 0; j < 16; j++) o[j] = 0.f;

    const int ntiles = causal ? (qt + 1) : (SEQ / 64);
    const float scale = 0.125f;          // 1/sqrt(64)
    const unsigned char* mbase = mask + (size_t)b * SEQ * SEQ + (size_t)gr * SEQ;

    for (int t = 0; t < ntiles; t++) {
        const int k0 = t << 6;
        __syncthreads();   // previous tile fully consumed before overwrite
#pragma unroll
        for (int it = 0; it < 4; it++) {
            int f = tid + (it << 8);
            int r = f >> 4;
            int c4 = (f & 15) << 2;
            *(float4*)&Ks[r][c4] = *(const float4*)&Kg[(k0 + r) * DK + c4];
            *(float4*)&Vs[r][c4] = *(const float4*)&Vg[(k0 + r) * DK + c4];
        }
        __syncthreads();

        // scores: s[cc] for columns c = q*16 + cc
        float s[16];
#pragma unroll
        for (int cc = 0; cc < 16; cc++) s[cc] = 0.f;
#pragma unroll
        for (int k4 = 0; k4 < 16; k4++) {
            float4 qv = *(const float4*)&Qs[row][k4 << 2];
#pragma unroll
            for (int cc = 0; cc < 16; cc++) {
                float4 kv = *(const float4*)&Ks[(q << 4) + cc][k4 << 2];
                s[cc] += qv.x * kv.x + qv.y * kv.y + qv.z * kv.z + qv.w * kv.w;
            }
        }

        // mask (boolean attention_mask + causal)
        uint4 mv = *(const uint4*)(mbase + k0 + (q << 4));
        const unsigned char* mb = (const unsigned char*)&mv;
#pragma unroll
        for (int cc = 0; cc < 16; cc++) {
            int gc = k0 + (q << 4) + cc;
            float sv = s[cc] * scale;
            bool dead = (mb[cc] != 0) || (causal && (gc > gr));
            s[cc] = dead ? -1e30f : sv;
        }

        // online softmax over the row (quad reduction)
        float tmax = s[0];
#pragma unroll
        for (int cc = 1; cc < 16; cc++) tmax = fmaxf(tmax, s[cc]);
        tmax = fmaxf(tmax, __shfl_xor_sync(0xffffffffu, tmax, 1));
        tmax = fmaxf(tmax, __shfl_xor_sync(0xffffffffu, tmax, 2));
        float m_new = fmaxf(m_i, tmax);
        float sf = __expf(m_i - m_new);
        float rs = 0.f;
#pragma unroll
        for (int cc = 0; cc < 16; cc++) {
            float p = __expf(s[cc] - m_new);
            s[cc] = p;
            rs += p;
        }
        rs += __shfl_xor_sync(0xffffffffu, rs, 1);
        rs += __shfl_xor_sync(0xffffffffu, rs, 2);
        l_i = l_i * sf + rs;
        m_i = m_new;
#pragma unroll
        for (int j = 0; j < 16; j++) o[j] *= sf;

        // write P (only this quad reads its row back -> warp-level sync only)
        *(float4*)&Ps[row][(q << 4) + 0]  = make_float4(s[0],  s[1],  s[2],  s[3]);
        *(float4*)&Ps[row][(q << 4) + 4]  = make_float4(s[4],  s[5],  s[6],  s[7]);
        *(float4*)&Ps[row][(q << 4) + 8]  = make_float4(s[8],  s[9],  s[10], s[11]);
        *(float4*)&Ps[row][(q << 4) + 12] = make_float4(s[12], s[13], s[14], s[15]);
        __syncwarp();

        // O[row][j] += sum_c P[row][c] * V[c][j], j = q*16 .. q*16+15
#pragma unroll 8
        for (int c = 0; c < 64; c++) {
            float p = Ps[row][c];
#pragma unroll
            for (int jj = 0; jj < 4; jj++) {
                float4 vv = *(const float4*)&Vs[c][(q << 4) + (jj << 2)];
                o[(jj << 2) + 0] += p * vv.x;
                o[(jj << 2) + 1] += p * vv.y;
                o[(jj << 2) + 2] += p * vv.z;
                o[(jj << 2) + 3] += p * vv.w;
            }
        }
    }

    // epilogue: normalize and write to g_O[b, gr, h*64 + q*16 ..]
    float inv = (l_i > 0.f) ? (1.f / l_i) : 0.f;
    float* Og = g_O + ((size_t)b * SEQ + gr) * DMODEL + (h << 6) + (q << 4);
#pragma unroll
    for (int jj = 0; jj < 4; jj++) {
        float4 st;
        st.x = o[(jj << 2) + 0] * inv;
        st.y = o[(jj << 2) + 1] * inv;
        st.z = o[(jj << 2) + 2] * inv;
        st.w = o[(jj << 2) + 3] * inv;
        *(float4*)&Og[jj << 2] = st;
    }
}

// ---------------------------------------------------------------------------
extern "C" void kernel_launch(void* const* d_in, const int* in_sizes, int n_in,
                              void* d_out, int out_size)
{
    const float* query = (const float*)d_in[0];
    const float* key   = (const float*)d_in[1];
    const float* value = (const float*)d_in[2];
    const unsigned char* mask = (const unsigned char*)d_in[3];
    const float* Wq    = (const float*)d_in[4];
    const float* Wk    = (const float*)d_in[5];
    const float* Wv    = (const float*)d_in[6];
    const float* Wout  = (const float*)d_in[7];
    const float* b_out = (const float*)d_in[8];
    const int* is_causal = (const int*)d_in[9];
    float* out = (float*)d_out;

    static const int ATTN_SMEM = 4 * 64 * APAD * (int)sizeof(float); // 69632
    cudaFuncSetAttribute(attn_kernel, cudaFuncAttributeMaxDynamicSharedMemorySize, ATTN_SMEM);

    dim3 ggrid(DMODEL / 128, MROWS / 128);   // (8, 32)
    gemm_kernel<<<ggrid, 256>>>(query, Wq, nullptr, nullptr, 0);
    gemm_kernel<<<ggrid, 256>>>(key,   Wk, nullptr, nullptr, 1);
    gemm_kernel<<<ggrid, 256>>>(value, Wv, nullptr, nullptr, 2);

    dim3 agrid(SEQ / 64, BATCH * NHEAD);     // (32, 32)
    attn_kernel<<<agrid, 256, ATTN_SMEM>>>(mask, is_causal);

    gemm_kernel<<<ggrid, 256>>>(nullptr, Wout, b_out, out, 3);
}

// round 2
// speedup vs baseline: 3.6853x; 3.6853x over previous
#include <cuda_runtime.h>
#include <cstdint>

// Problem constants (fixed by the reference setup_inputs)
#define BATCH 2
#define SEQ   2048
#define DMODEL 1024
#define NHEAD 16
#define DK    64
#define MROWS (BATCH * SEQ)   // 4096

// Scratch: Q,K,V in [B,H,S,DK], O in [B,S,D]
__device__ float g_Q[BATCH * NHEAD * SEQ * DK];
__device__ float g_K[BATCH * NHEAD * SEQ * DK];
__device__ float g_V[BATCH * NHEAD * SEQ * DK];
__device__ float g_O[BATCH * SEQ * DMODEL];

// ---------------------------------------------------------------------------
// tf32 helpers (legacy mma.sync path, valid on sm_100a)
// ---------------------------------------------------------------------------
__device__ __forceinline__ unsigned f2tf32(float f) {
    unsigned u;
    asm("cvt.rna.tf32.f32 %0, %1;" : "=r"(u) : "f"(f));
    return u;
}

__device__ __forceinline__ void mma_tf32(float c[4], const unsigned a[4], const unsigned b[2]) {
    asm volatile(
        "mma.sync.aligned.m16n8k8.row.col.f32.tf32.tf32.f32 "
        "{%0,%1,%2,%3}, {%4,%5,%6,%7}, {%8,%9}, {%0,%1,%2,%3};\n"
        : "+f"(c[0]), "+f"(c[1]), "+f"(c[2]), "+f"(c[3])
        : "r"(a[0]), "r"(a[1]), "r"(a[2]), "r"(a[3]), "r"(b[0]), "r"(b[1]));
}

// ---------------------------------------------------------------------------
// GEMM: C[M,N] = A[M,K] @ W[N,K]^T  (fp32 SIMT, unchanged from R1)
// ---------------------------------------------------------------------------
#define GBK 16
#define GPAD 132

__global__ __launch_bounds__(256, 2) void gemm_kernel(
    const float* __restrict__ A, const float* __restrict__ W,
    const float* __restrict__ bias, float* __restrict__ outFlat, int mode)
{
    __shared__ float As[GBK][GPAD];
    __shared__ float Ws[GBK][GPAD];

    const float* Ap = (mode == 3) ? g_O : A;

    const int tid = threadIdx.x;
    const int tx = tid & 15;
    const int ty = tid >> 4;
    const int m0 = blockIdx.y << 7;
    const int n0 = blockIdx.x << 7;

    float acc[8][8];
#pragma unroll
    for (int i = 0; i < 8; i++)
#pragma unroll
        for (int j = 0; j < 8; j++) acc[i][j] = 0.f;

    for (int k0 = 0; k0 < DMODEL; k0 += GBK) {
#pragma unroll
        for (int it = 0; it < 2; it++) {
            int f = tid + (it << 8);
            int r = f >> 2;
            int c4 = (f & 3) << 2;
            float4 va = *(const float4*)&Ap[(m0 + r) * DMODEL + k0 + c4];
            As[c4 + 0][r] = va.x; As[c4 + 1][r] = va.y;
            As[c4 + 2][r] = va.z; As[c4 + 3][r] = va.w;
            float4 vw = *(const float4*)&W[(n0 + r) * DMODEL + k0 + c4];
            Ws[c4 + 0][r] = vw.x; Ws[c4 + 1][r] = vw.y;
            Ws[c4 + 2][r] = vw.z; Ws[c4 + 3][r] = vw.w;
        }
        __syncthreads();

#pragma unroll
        for (int kk = 0; kk < GBK; kk++) {
            float a[8], b[8];
            float4 a0 = *(const float4*)&As[kk][ty << 2];
            float4 a1 = *(const float4*)&As[kk][64 + (ty << 2)];
            float4 b0 = *(const float4*)&Ws[kk][tx << 2];
            float4 b1 = *(const float4*)&Ws[kk][64 + (tx << 2)];
            a[0] = a0.x; a[1] = a0.y; a[2] = a0.z; a[3] = a0.w;
            a[4] = a1.x; a[5] = a1.y; a[6] = a1.z; a[7] = a1.w;
            b[0] = b0.x; b[1] = b0.y; b[2] = b0.z; b[3] = b0.w;
            b[4] = b1.x; b[5] = b1.y; b[6] = b1.z; b[7] = b1.w;
#pragma unroll
            for (int i = 0; i < 8; i++)
#pragma unroll
                for (int j = 0; j < 8; j++) acc[i][j] += a[i] * b[j];
        }
        __syncthreads();
    }

    if (mode == 3) {
#pragma unroll
        for (int i = 0; i < 8; i++) {
            int r = (i < 4) ? ((ty << 2) + i) : (64 + (ty << 2) + i - 4);
            int m = m0 + r;
#pragma unroll
            for (int jg = 0; jg < 2; jg++) {
                int c = (jg << 6) + (tx << 2);
                int n = n0 + c;
                float4 o;
                o.x = acc[i][(jg << 2) + 0] + bias[n + 0];
                o.y = acc[i][(jg << 2) + 1] + bias[n + 1];
                o.z = acc[i][(jg << 2) + 2] + bias[n + 2];
                o.w = acc[i][(jg << 2) + 3] + bias[n + 3];
                *(float4*)&outFlat[m * DMODEL + n] = o;
            }
        }
    } else {
        float* outp = (mode == 0) ? g_Q : ((mode == 1) ? g_K : g_V);
#pragma unroll
        for (int i = 0; i < 8; i++) {
            int r = (i < 4) ? ((ty << 2) + i) : (64 + (ty << 2) + i - 4);
            int m = m0 + r;
            int bb = m >> 11;
            int s  = m & 2047;
#pragma unroll
            for (int jg = 0; jg < 2; jg++) {
                int c = (jg << 6) + (tx << 2);
                int n = n0 + c;
                int h = n >> 6;
                int d = n & 63;
                float4 o;
                o.x = acc[i][(jg << 2) + 0];
                o.y = acc[i][(jg << 2) + 1];
                o.z = acc[i][(jg << 2) + 2];
                o.w = acc[i][(jg << 2) + 3];
                *(float4*)&outp[(((bb << 4) + h) * SEQ + s) * DK + d] = o;
            }
        }
    }
}

// ---------------------------------------------------------------------------
// Flash attention with tf32 mma.sync (m16n8k8).
// CTA: 128 query rows, 8 warps (warp w owns rows [16w, 16w+16)).
// KV tiles of 64. Q fragments live in registers; the Q smem region is
// reused as the P buffer (warp-local rows -> only __syncwarp needed).
// smem strides chosen for conflict-free fragment LDS:
//   QPs stride 72 (A-frag read bank = 8g+tg), Ks stride 68 (4g+tg),
//   Vs stride 72 (8tg+g).
// ---------------------------------------------------------------------------
#define AQP_ST 72
#define AK_ST  68
#define AV_ST  72
#define ATTN_SMEM_BYTES ((128 * AQP_ST + 64 * AK_ST + 64 * AV_ST) * 4)  // 72704

__global__ __launch_bounds__(256) void attn_mma_kernel(
    const unsigned char* __restrict__ mask, const int* __restrict__ is_causal_p)
{
    extern __shared__ unsigned sm_u[];
    unsigned* QPs = sm_u;                    // [128][72] : Q (tf32) then P
    unsigned* Ks  = QPs + 128 * AQP_ST;      // [64][68]
    unsigned* Vs  = Ks + 64 * AK_ST;         // [64][72]

    const int bh = blockIdx.y;               // 0..31
    const int qt = blockIdx.x;               // 0..15
    const int b  = bh >> 4;
    const int h  = bh & 15;
    const int causal = is_causal_p[0];
    const int q0 = qt << 7;                  // 128 rows per CTA

    const int tid  = threadIdx.x;
    const int warp = tid >> 5;
    const int lane = tid & 31;
    const int g    = lane >> 2;              // group id 0..7
    const int tg   = lane & 3;               // thread in group

    const float* Qg = g_Q + ((size_t)bh * SEQ + q0) * DK;
    const float* Kg = g_K + (size_t)bh * SEQ * DK;
    const float* Vg = g_V + (size_t)bh * SEQ * DK;

    // ---- Load Q tile (128 x 64) to smem as tf32 ----
#pragma unroll
    for (int it = 0; it < 8; it++) {
        int f = tid + (it << 8);             // 0..2047 float4s
        int r = f >> 4;
        int c4 = (f & 15) << 2;
        float4 v = *(const float4*)&Qg[r * DK + c4];
        uint4 u;
        u.x = f2tf32(v.x); u.y = f2tf32(v.y);
        u.z = f2tf32(v.z); u.w = f2tf32(v.w);
        *(uint4*)&QPs[r * AQP_ST + c4] = u;
    }
    __syncthreads();

    // ---- Q fragments into registers: 8 k-steps x 4 regs ----
    const int r0 = (warp << 4) + g;          // local row of a0/a2
    const int r1 = r0 + 8;                   // local row of a1/a3
    unsigned qf[8][4];
#pragma unroll
    for (int ks = 0; ks < 8; ks++) {
        int k = (ks << 3) + tg;
        qf[ks][0] = QPs[r0 * AQP_ST + k];
        qf[ks][1] = QPs[r1 * AQP_ST + k];
        qf[ks][2] = QPs[r0 * AQP_ST + k + 4];
        qf[ks][3] = QPs[r1 * AQP_ST + k + 4];
    }

    const int gr0 = q0 + r0;                 // global query rows
    const int gr1 = q0 + r1;
    const unsigned char* mrow0 = mask + (size_t)b * SEQ * SEQ + (size_t)gr0 * SEQ;
    const unsigned char* mrow1 = mask + (size_t)b * SEQ * SEQ + (size_t)gr1 * SEQ;

    float m0 = -1e30f, m1 = -1e30f, l0 = 0.f, l1 = 0.f;
    float of[8][4];
#pragma unroll
    for (int nf = 0; nf < 8; nf++)
#pragma unroll
        for (int j = 0; j < 4; j++) of[nf][j] = 0.f;

    const int ntiles = causal ? (2 * qt + 2) : (SEQ / 64);
    const float scale = 0.125f;              // 1/sqrt(64)

    for (int t = 0; t < ntiles; t++) {
        const int k0 = t << 6;
        __syncthreads();                      // prev tile fully consumed
        // ---- load K,V tiles (64x64 each) as tf32 ----
#pragma unroll
        for (int it = 0; it < 4; it++) {
            int f = tid + (it << 8);         // 0..1023 float4s
            int r = f >> 4;
            int c4 = (f & 15) << 2;
            float4 kv = *(const float4*)&Kg[(k0 + r) * DK + c4];
            uint4 ku;
            ku.x = f2tf32(kv.x); ku.y = f2tf32(kv.y);
            ku.z = f2tf32(kv.z); ku.w = f2tf32(kv.w);
            *(uint4*)&Ks[r * AK_ST + c4] = ku;
            float4 vv = *(const float4*)&Vg[(k0 + r) * DK + c4];
            uint4 vu;
            vu.x = f2tf32(vv.x); vu.y = f2tf32(vv.y);
            vu.z = f2tf32(vv.z); vu.w = f2tf32(vv.w);
            *(uint4*)&Vs[r * AV_ST + c4] = vu;
        }
        __syncthreads();

        // ---- S = Q @ K^T : warp computes 16x64 ----
        float s[8][4];
#pragma unroll
        for (int nf = 0; nf < 8; nf++)
#pragma unroll
            for (int j = 0; j < 4; j++) s[nf][j] = 0.f;

#pragma unroll
        for (int nf = 0; nf < 8; nf++) {
            int nrow = (nf << 3) + g;         // K row (= S column block)
#pragma unroll
            for (int ks = 0; ks < 8; ks++) {
                unsigned bb[2];
                int k = (ks << 3) + tg;
                bb[0] = Ks[nrow * AK_ST + k];
                bb[1] = Ks[nrow * AK_ST + k + 4];
                mma_tf32(s[nf], qf[ks], bb);
            }
        }

        // ---- scale + mask ----
#pragma unroll
        for (int nf = 0; nf < 8; nf++) {
            int col = k0 + (nf << 3) + (tg << 1);
            uchar2 mb0 = *(const uchar2*)(mrow0 + col);
            uchar2 mb1 = *(const uchar2*)(mrow1 + col);
            bool d00 = mb0.x || (causal && (col     > gr0));
            bool d01 = mb0.y || (causal && (col + 1 > gr0));
            bool d10 = mb1.x || (causal && (col     > gr1));
            bool d11 = mb1.y || (causal && (col + 1 > gr1));
            s[nf][0] = d00 ? -1e30f : s[nf][0] * scale;
            s[nf][1] = d01 ? -1e30f : s[nf][1] * scale;
            s[nf][2] = d10 ? -1e30f : s[nf][2] * scale;
            s[nf][3] = d11 ? -1e30f : s[nf][3] * scale;
        }

        // ---- online softmax (two rows per lane, quad reduce) ----
        float mx0 = -1e30f, mx1 = -1e30f;
#pragma unroll
        for (int nf = 0; nf < 8; nf++) {
            mx0 = fmaxf(mx0, fmaxf(s[nf][0], s[nf][1]));
            mx1 = fmaxf(mx1, fmaxf(s[nf][2], s[nf][3]));
        }
        mx0 = fmaxf(mx0, __shfl_xor_sync(0xffffffffu, mx0, 1));
        mx0 = fmaxf(mx0, __shfl_xor_sync(0xffffffffu, mx0, 2));
        mx1 = fmaxf(mx1, __shfl_xor_sync(0xffffffffu, mx1, 1));
        mx1 = fmaxf(mx1, __shfl_xor_sync(0xffffffffu, mx1, 2));
        float m0n = fmaxf(m0, mx0);
        float m1n = fmaxf(m1, mx1);
        float sf0 = __expf(m0 - m0n);
        float sf1 = __expf(m1 - m1n);
        float rs0 = 0.f, rs1 = 0.f;
#pragma unroll
        for (int nf = 0; nf < 8; nf++) {
            float p0 = __expf(s[nf][0] - m0n);
            float p1 = __expf(s[nf][1] - m0n);
            float p2 = __expf(s[nf][2] - m1n);
            float p3 = __expf(s[nf][3] - m1n);
            s[nf][0] = p0; s[nf][1] = p1; s[nf][2] = p2; s[nf][3] = p3;
            rs0 += p0 + p1;
            rs1 += p2 + p3;
        }
        rs0 += __shfl_xor_sync(0xffffffffu, rs0, 1);
        rs0 += __shfl_xor_sync(0xffffffffu, rs0, 2);
        rs1 += __shfl_xor_sync(0xffffffffu, rs1, 1);
        rs1 += __shfl_xor_sync(0xffffffffu, rs1, 2);
        l0 = l0 * sf0 + rs0;
        l1 = l1 * sf1 + rs1;
        m0 = m0n; m1 = m1n;
#pragma unroll
        for (int nf = 0; nf < 8; nf++) {
            of[nf][0] *= sf0; of[nf][1] *= sf0;
            of[nf][2] *= sf1; of[nf][3] *= sf1;
        }

        // ---- write P (tf32) to warp-local rows of QPs ----
#pragma unroll
        for (int nf = 0; nf < 8; nf++) {
            int c = (nf << 3) + (tg << 1);
            uint2 p0; p0.x = f2tf32(s[nf][0]); p0.y = f2tf32(s[nf][1]);
            uint2 p1; p1.x = f2tf32(s[nf][2]); p1.y = f2tf32(s[nf][3]);
            *(uint2*)&QPs[r0 * AQP_ST + c] = p0;
            *(uint2*)&QPs[r1 * AQP_ST + c] = p1;
        }
        __syncwarp();

        // ---- O += P @ V ----
#pragma unroll
        for (int ks = 0; ks < 8; ks++) {
            unsigned a[4];
            int k = (ks << 3) + tg;
            a[0] = QPs[r0 * AQP_ST + k];
            a[1] = QPs[r1 * AQP_ST + k];
            a[2] = QPs[r0 * AQP_ST + k + 4];
            a[3] = QPs[r1 * AQP_ST + k + 4];
#pragma unroll
            for (int nf = 0; nf < 8; nf++) {
                unsigned bb[2];
                int n = (nf << 3) + g;
                bb[0] = Vs[((ks << 3) + tg) * AV_ST + n];
                bb[1] = Vs[((ks << 3) + tg + 4) * AV_ST + n];
                mma_tf32(of[nf], a, bb);
            }
        }
        __syncwarp();                         // P reads done before next overwrite
    }

    // ---- epilogue: normalize, write to g_O[b, row, h*64 + d] ----
    float inv0 = (m0 > -1e29f && l0 > 0.f) ? (1.f / l0) : 0.f;
    float inv1 = (m1 > -1e29f && l1 > 0.f) ? (1.f / l1) : 0.f;
    float* Og0 = g_O + ((size_t)b * SEQ + gr0) * DMODEL + (h << 6);
    float* Og1 = g_O + ((size_t)b * SEQ + gr1) * DMODEL + (h << 6);
#pragma unroll
    for (int nf = 0; nf < 8; nf++) {
        int c = (nf << 3) + (tg << 1);
        float2 w0; w0.x = of[nf][0] * inv0; w0.y = of[nf][1] * inv0;
        float2 w1; w1.x = of[nf][2] * inv1; w1.y = of[nf][3] * inv1;
        *(float2*)&Og0[c] = w0;
        *(float2*)&Og1[c] = w1;
    }
}

// ---------------------------------------------------------------------------
extern "C" void kernel_launch(void* const* d_in, const int* in_sizes, int n_in,
                              void* d_out, int out_size)
{
    const float* query = (const float*)d_in[0];
    const float* key   = (const float*)d_in[1];
    const float* value = (const float*)d_in[2];
    const unsigned char* mask = (const unsigned char*)d_in[3];
    const float* Wq    = (const float*)d_in[4];
    const float* Wk    = (const float*)d_in[5];
    const float* Wv    = (const float*)d_in[6];
    const float* Wout  = (const float*)d_in[7];
    const float* b_out = (const float*)d_in[8];
    const int* is_causal = (const int*)d_in[9];
    float* out = (float*)d_out;

    cudaFuncSetAttribute(attn_mma_kernel,
                         cudaFuncAttributeMaxDynamicSharedMemorySize, ATTN_SMEM_BYTES);

    dim3 ggrid(DMODEL / 128, MROWS / 128);   // (8, 32)
    gemm_kernel<<<ggrid, 256>>>(query, Wq, nullptr, nullptr, 0);
    gemm_kernel<<<ggrid, 256>>>(key,   Wk, nullptr, nullptr, 1);
    gemm_kernel<<<ggrid, 256>>>(value, Wv, nullptr, nullptr, 2);

    dim3 agrid(SEQ / 128, BATCH * NHEAD);    // (16, 32)
    attn_mma_kernel<<<agrid, 256, ATTN_SMEM_BYTES>>>(mask, is_causal);

    gemm_kernel<<<ggrid, 256>>>(nullptr, Wout, b_out, out, 3);
}

// round 3
// speedup vs baseline: 4.2692x; 1.1585x over previous
#include <cuda_runtime.h>
#include <cstdint>

// Problem constants (fixed by the reference setup_inputs)
#define BATCH 2
#define SEQ   2048
#define DMODEL 1024
#define NHEAD 16
#define DK    64
#define MROWS (BATCH * SEQ)   // 4096

// Scratch: Q,K,V in [B,H,S,DK], O in [B,S,D]
__device__ float g_Q[BATCH * NHEAD * SEQ * DK];
__device__ float g_K[BATCH * NHEAD * SEQ * DK];
__device__ float g_V[BATCH * NHEAD * SEQ * DK];
__device__ float g_O[BATCH * SEQ * DMODEL];

// ---------------------------------------------------------------------------
// tf32 helpers (legacy mma.sync path, valid on sm_100a)
// ---------------------------------------------------------------------------
__device__ __forceinline__ unsigned f2tf32(float f) {
    unsigned u;
    asm("cvt.rna.tf32.f32 %0, %1;" : "=r"(u) : "f"(f));
    return u;
}

__device__ __forceinline__ void mma_tf32(float c[4], const unsigned a[4], const unsigned b[2]) {
    asm volatile(
        "mma.sync.aligned.m16n8k8.row.col.f32.tf32.tf32.f32 "
        "{%0,%1,%2,%3}, {%4,%5,%6,%7}, {%8,%9}, {%0,%1,%2,%3};\n"
        : "+f"(c[0]), "+f"(c[1]), "+f"(c[2]), "+f"(c[3])
        : "r"(a[0]), "r"(a[1]), "r"(a[2]), "r"(a[3]), "r"(b[0]), "r"(b[1]));
}

// ---------------------------------------------------------------------------
// Tensor-core GEMM with 3xTF32 compensation (near-fp32 accuracy).
// C[M,N] = A[M,K] @ W[N,K]^T.  M=4096, N=1024, K=1024.
// CTA 128x128, K-chunk 16. 8 warps as 4(M) x 2(N): warp tile 32x64.
// Smem layout [row][TPAD=20] words: frag reads bank = (20g+tg)%32, all
// 32 banks distinct -> conflict-free LDS.
// mode 0/1/2: head-split output to g_Q/g_K/g_V; mode 3: +bias to outFlat.
// ---------------------------------------------------------------------------
#define TPAD 20

__global__ __launch_bounds__(256, 2) void gemm_tc_kernel(
    const float* __restrict__ A, const float* __restrict__ W,
    const float* __restrict__ bias, float* __restrict__ outFlat, int mode)
{
    __shared__ unsigned Ah[128][TPAD];
    __shared__ unsigned Al[128][TPAD];
    __shared__ unsigned Wh[128][TPAD];
    __shared__ unsigned Wl[128][TPAD];

    const float* Ap = (mode == 3) ? g_O : A;

    const int tid  = threadIdx.x;
    const int warp = tid >> 5;
    const int lane = tid & 31;
    const int g    = lane >> 2;     // 0..7
    const int tg   = lane & 3;      // 0..3
    const int wm   = warp >> 1;     // 0..3
    const int wn   = warp & 1;      // 0..1
    const int m0   = blockIdx.y << 7;
    const int n0   = blockIdx.x << 7;

    // loader mapping: 2 float4 per matrix per chunk
    const int lr  = tid >> 2;            // row 0..63 (f=tid), +64 for second
    const int lk4 = (tid & 3) << 2;      // k offset 0,4,8,12

    float acc[2][8][4];
#pragma unroll
    for (int mf = 0; mf < 2; mf++)
#pragma unroll
        for (int nf = 0; nf < 8; nf++)
#pragma unroll
            for (int j = 0; j < 4; j++) acc[mf][nf][j] = 0.f;

    // prefetch chunk 0
    float4 aR[2], wR[2];
#pragma unroll
    for (int it = 0; it < 2; it++) {
        int r = lr + (it << 6);
        aR[it] = *(const float4*)&Ap[(m0 + r) * DMODEL + lk4];
        wR[it] = *(const float4*)&W[(n0 + r) * DMODEL + lk4];
    }

    for (int k0 = 0; k0 < DMODEL; k0 += 16) {
        __syncthreads();   // previous chunk fully consumed
        // store hi/lo split to smem
#pragma unroll
        for (int it = 0; it < 2; it++) {
            int r = lr + (it << 6);
            const float* av = (const float*)&aR[it];
            const float* wv = (const float*)&wR[it];
            uint4 ahi, alo, whi, wlo;
            unsigned* ah = (unsigned*)&ahi; unsigned* al = (unsigned*)&alo;
            unsigned* wh = (unsigned*)&whi; unsigned* wl = (unsigned*)&wlo;
#pragma unroll
            for (int j = 0; j < 4; j++) {
                unsigned h = f2tf32(av[j]);
                ah[j] = h;
                al[j] = f2tf32(av[j] - __uint_as_float(h));
                unsigned h2 = f2tf32(wv[j]);
                wh[j] = h2;
                wl[j] = f2tf32(wv[j] - __uint_as_float(h2));
            }
            *(uint4*)&Ah[r][lk4] = ahi;
            *(uint4*)&Al[r][lk4] = alo;
            *(uint4*)&Wh[r][lk4] = whi;
            *(uint4*)&Wl[r][lk4] = wlo;
        }
        __syncthreads();

        // prefetch next chunk
        if (k0 + 16 < DMODEL) {
#pragma unroll
            for (int it = 0; it < 2; it++) {
                int r = lr + (it << 6);
                aR[it] = *(const float4*)&Ap[(m0 + r) * DMODEL + k0 + 16 + lk4];
                wR[it] = *(const float4*)&W[(n0 + r) * DMODEL + k0 + 16 + lk4];
            }
        }

        // compute: 2 k-steps of 8
#pragma unroll
        for (int ks = 0; ks < 2; ks++) {
            const int kk = (ks << 3) + tg;
            unsigned ah[2][4], al[2][4];
#pragma unroll
            for (int mf = 0; mf < 2; mf++) {
                int r0 = (wm << 5) + (mf << 4) + g;
                ah[mf][0] = Ah[r0][kk];     ah[mf][1] = Ah[r0 + 8][kk];
                ah[mf][2] = Ah[r0][kk + 4]; ah[mf][3] = Ah[r0 + 8][kk + 4];
                al[mf][0] = Al[r0][kk];     al[mf][1] = Al[r0 + 8][kk];
                al[mf][2] = Al[r0][kk + 4]; al[mf][3] = Al[r0 + 8][kk + 4];
            }
#pragma unroll
            for (int nf = 0; nf < 8; nf++) {
                int nr = (wn << 6) + (nf << 3) + g;
                unsigned bh[2], bl[2];
                bh[0] = Wh[nr][kk]; bh[1] = Wh[nr][kk + 4];
                bl[0] = Wl[nr][kk]; bl[1] = Wl[nr][kk + 4];
#pragma unroll
                for (int mf = 0; mf < 2; mf++) {
                    mma_tf32(acc[mf][nf], ah[mf], bl);   // hi*lo
                    mma_tf32(acc[mf][nf], al[mf], bh);   // lo*hi
                    mma_tf32(acc[mf][nf], ah[mf], bh);   // hi*hi
                }
            }
        }
    }

    // ---- epilogue ----
    if (mode == 3) {
#pragma unroll
        for (int mf = 0; mf < 2; mf++) {
            int r0 = m0 + (wm << 5) + (mf << 4) + g;
#pragma unroll
            for (int nf = 0; nf < 8; nf++) {
                int n = n0 + (wn << 6) + (nf << 3) + (tg << 1);
                float2 bi = *(const float2*)&bias[n];
                float2 w0, w1;
                w0.x = acc[mf][nf][0] + bi.x; w0.y = acc[mf][nf][1] + bi.y;
                w1.x = acc[mf][nf][2] + bi.x; w1.y = acc[mf][nf][3] + bi.y;
                *(float2*)&outFlat[r0 * DMODEL + n] = w0;
                *(float2*)&outFlat[(r0 + 8) * DMODEL + n] = w1;
            }
        }
    } else {
        float* outp = (mode == 0) ? g_Q : ((mode == 1) ? g_K : g_V);
#pragma unroll
        for (int mf = 0; mf < 2; mf++) {
            int m = m0 + (wm << 5) + (mf << 4) + g;
            int bb0 = m >> 11;
            int s   = m & 2047;
            int mb1 = m + 8;
            int bb1 = mb1 >> 11;
            int s1  = mb1 & 2047;
#pragma unroll
            for (int nf = 0; nf < 8; nf++) {
                int n = n0 + (wn << 6) + (nf << 3) + (tg << 1);
                int h = n >> 6;
                int d = n & 63;
                float2 w0, w1;
                w0.x = acc[mf][nf][0]; w0.y = acc[mf][nf][1];
                w1.x = acc[mf][nf][2]; w1.y = acc[mf][nf][3];
                *(float2*)&outp[(((bb0 << 4) + h) * SEQ + s) * DK + d] = w0;
                *(float2*)&outp[(((bb1 << 4) + h) * SEQ + s1) * DK + d] = w1;
            }
        }
    }
}

// ---------------------------------------------------------------------------
// Flash attention with tf32 mma.sync (m16n8k8). Unchanged from R2.
// ---------------------------------------------------------------------------
#define AQP_ST 72
#define AK_ST  68
#define AV_ST  72
#define ATTN_SMEM_BYTES ((128 * AQP_ST + 64 * AK_ST + 64 * AV_ST) * 4)  // 72704

__global__ __launch_bounds__(256) void attn_mma_kernel(
    const unsigned char* __restrict__ mask, const int* __restrict__ is_causal_p)
{
    extern __shared__ unsigned sm_u[];
    unsigned* QPs = sm_u;                    // [128][72] : Q (tf32) then P
    unsigned* Ks  = QPs + 128 * AQP_ST;      // [64][68]
    unsigned* Vs  = Ks + 64 * AK_ST;         // [64][72]

    const int bh = blockIdx.y;
    const int qt = blockIdx.x;
    const int b  = bh >> 4;
    const int h  = bh & 15;
    const int causal = is_causal_p[0];
    const int q0 = qt << 7;

    const int tid  = threadIdx.x;
    const int warp = tid >> 5;
    const int lane = tid & 31;
    const int g    = lane >> 2;
    const int tg   = lane & 3;

    const float* Qg = g_Q + ((size_t)bh * SEQ + q0) * DK;
    const float* Kg = g_K + (size_t)bh * SEQ * DK;
    const float* Vg = g_V + (size_t)bh * SEQ * DK;

#pragma unroll
    for (int it = 0; it < 8; it++) {
        int f = tid + (it << 8);
        int r = f >> 4;
        int c4 = (f & 15) << 2;
        float4 v = *(const float4*)&Qg[r * DK + c4];
        uint4 u;
        u.x = f2tf32(v.x); u.y = f2tf32(v.y);
        u.z = f2tf32(v.z); u.w = f2tf32(v.w);
        *(uint4*)&QPs[r * AQP_ST + c4] = u;
    }
    __syncthreads();

    const int r0 = (warp << 4) + g;
    const int r1 = r0 + 8;
    unsigned qf[8][4];
#pragma unroll
    for (int ks = 0; ks < 8; ks++) {
        int k = (ks << 3) + tg;
        qf[ks][0] = QPs[r0 * AQP_ST + k];
        qf[ks][1] = QPs[r1 * AQP_ST + k];
        qf[ks][2] = QPs[r0 * AQP_ST + k + 4];
        qf[ks][3] = QPs[r1 * AQP_ST + k + 4];
    }

    const int gr0 = q0 + r0;
    const int gr1 = q0 + r1;
    const unsigned char* mrow0 = mask + (size_t)b * SEQ * SEQ + (size_t)gr0 * SEQ;
    const unsigned char* mrow1 = mask + (size_t)b * SEQ * SEQ + (size_t)gr1 * SEQ;

    float m0 = -1e30f, m1 = -1e30f, l0 = 0.f, l1 = 0.f;
    float of[8][4];
#pragma unroll
    for (int nf = 0; nf < 8; nf++)
#pragma unroll
        for (int j = 0; j < 4; j++) of[nf][j] = 0.f;

    const int ntiles = causal ? (2 * qt + 2) : (SEQ / 64);
    const float scale = 0.125f;

    for (int t = 0; t < ntiles; t++) {
        const int k0 = t << 6;
        __syncthreads();
#pragma unroll
        for (int it = 0; it < 4; it++) {
            int f = tid + (it << 8);
            int r = f >> 4;
            int c4 = (f & 15) << 2;
            float4 kv = *(const float4*)&Kg[(k0 + r) * DK + c4];
            uint4 ku;
            ku.x = f2tf32(kv.x); ku.y = f2tf32(kv.y);
            ku.z = f2tf32(kv.z); ku.w = f2tf32(kv.w);
            *(uint4*)&Ks[r * AK_ST + c4] = ku;
            float4 vv = *(const float4*)&Vg[(k0 + r) * DK + c4];
            uint4 vu;
            vu.x = f2tf32(vv.x); vu.y = f2tf32(vv.y);
            vu.z = f2tf32(vv.z); vu.w = f2tf32(vv.w);
            *(uint4*)&Vs[r * AV_ST + c4] = vu;
        }
        __syncthreads();

        float s[8][4];
#pragma unroll
        for (int nf = 0; nf < 8; nf++)
#pragma unroll
            for (int j = 0; j < 4; j++) s[nf][j] = 0.f;

#pragma unroll
        for (int nf = 0; nf < 8; nf++) {
            int nrow = (nf << 3) + g;
#pragma unroll
            for (int ks = 0; ks < 8; ks++) {
                unsigned bb[2];
                int k = (ks << 3) + tg;
                bb[0] = Ks[nrow * AK_ST + k];
                bb[1] = Ks[nrow * AK_ST + k + 4];
                mma_tf32(s[nf], qf[ks], bb);
            }
        }

#pragma unroll
        for (int nf = 0; nf < 8; nf++) {
            int col = k0 + (nf << 3) + (tg << 1);
            uchar2 mb0 = *(const uchar2*)(mrow0 + col);
            uchar2 mb1 = *(const uchar2*)(mrow1 + col);
            bool d00 = mb0.x || (causal && (col     > gr0));
            bool d01 = mb0.y || (causal && (col + 1 > gr0));
            bool d10 = mb1.x || (causal && (col     > gr1));
            bool d11 = mb1.y || (causal && (col + 1 > gr1));
            s[nf][0] = d00 ? -1e30f : s[nf][0] * scale;
            s[nf][1] = d01 ? -1e30f : s[nf][1] * scale;
            s[nf][2] = d10 ? -1e30f : s[nf][2] * scale;
            s[nf][3] = d11 ? -1e30f : s[nf][3] * scale;
        }

        float mx0 = -1e30f, mx1 = -1e30f;
#pragma unroll
        for (int nf = 0; nf < 8; nf++) {
            mx0 = fmaxf(mx0, fmaxf(s[nf][0], s[nf][1]));
            mx1 = fmaxf(mx1, fmaxf(s[nf][2], s[nf][3]));
        }
        mx0 = fmaxf(mx0, __shfl_xor_sync(0xffffffffu, mx0, 1));
        mx0 = fmaxf(mx0, __shfl_xor_sync(0xffffffffu, mx0, 2));
        mx1 = fmaxf(mx1, __shfl_xor_sync(0xffffffffu, mx1, 1));
        mx1 = fmaxf(mx1, __shfl_xor_sync(0xffffffffu, mx1, 2));
        float m0n = fmaxf(m0, mx0);
        float m1n = fmaxf(m1, mx1);
        float sf0 = __expf(m0 - m0n);
        float sf1 = __expf(m1 - m1n);
        float rs0 = 0.f, rs1 = 0.f;
#pragma unroll
        for (int nf = 0; nf < 8; nf++) {
            float p0 = __expf(s[nf][0] - m0n);
            float p1 = __expf(s[nf][1] - m0n);
            float p2 = __expf(s[nf][2] - m1n);
            float p3 = __expf(s[nf][3] - m1n);
            s[nf][0] = p0; s[nf][1] = p1; s[nf][2] = p2; s[nf][3] = p3;
            rs0 += p0 + p1;
            rs1 += p2 + p3;
        }
        rs0 += __shfl_xor_sync(0xffffffffu, rs0, 1);
        rs0 += __shfl_xor_sync(0xffffffffu, rs0, 2);
        rs1 += __shfl_xor_sync(0xffffffffu, rs1, 1);
        rs1 += __shfl_xor_sync(0xffffffffu, rs1, 2);
        l0 = l0 * sf0 + rs0;
        l1 = l1 * sf1 + rs1;
        m0 = m0n; m1 = m1n;
#pragma unroll
        for (int nf = 0; nf < 8; nf++) {
            of[nf][0] *= sf0; of[nf][1] *= sf0;
            of[nf][2] *= sf1; of[nf][3] *= sf1;
        }

#pragma unroll
        for (int nf = 0; nf < 8; nf++) {
            int c = (nf << 3) + (tg << 1);
            uint2 p0; p0.x = f2tf32(s[nf][0]); p0.y = f2tf32(s[nf][1]);
            uint2 p1; p1.x = f2tf32(s[nf][2]); p1.y = f2tf32(s[nf][3]);
            *(uint2*)&QPs[r0 * AQP_ST + c] = p0;
            *(uint2*)&QPs[r1 * AQP_ST + c] = p1;
        }
        __syncwarp();

#pragma unroll
        for (int ks = 0; ks < 8; ks++) {
            unsigned a[4];
            int k = (ks << 3) + tg;
            a[0] = QPs[r0 * AQP_ST + k];
            a[1] = QPs[r1 * AQP_ST + k];
            a[2] = QPs[r0 * AQP_ST + k + 4];
            a[3] = QPs[r1 * AQP_ST + k + 4];
#pragma unroll
            for (int nf = 0; nf < 8; nf++) {
                unsigned bb[2];
                int n = (nf << 3) + g;
                bb[0] = Vs[((ks << 3) + tg) * AV_ST + n];
                bb[1] = Vs[((ks << 3) + tg + 4) * AV_ST + n];
                mma_tf32(of[nf], a, bb);
            }
        }
        __syncwarp();
    }

    float inv0 = (m0 > -1e29f && l0 > 0.f) ? (1.f / l0) : 0.f;
    float inv1 = (m1 > -1e29f && l1 > 0.f) ? (1.f / l1) : 0.f;
    float* Og0 = g_O + ((size_t)b * SEQ + gr0) * DMODEL + (h << 6);
    float* Og1 = g_O + ((size_t)b * SEQ + gr1) * DMODEL + (h << 6);
#pragma unroll
    for (int nf = 0; nf < 8; nf++) {
        int c = (nf << 3) + (tg << 1);
        float2 w0; w0.x = of[nf][0] * inv0; w0.y = of[nf][1] * inv0;
        float2 w1; w1.x = of[nf][2] * inv1; w1.y = of[nf][3] * inv1;
        *(float2*)&Og0[c] = w0;
        *(float2*)&Og1[c] = w1;
    }
}

// ---------------------------------------------------------------------------
extern "C" void kernel_launch(void* const* d_in, const int* in_sizes, int n_in,
                              void* d_out, int out_size)
{
    const float* query = (const float*)d_in[0];
    const float* key   = (const float*)d_in[1];
    const float* value = (const float*)d_in[2];
    const unsigned char* mask = (const unsigned char*)d_in[3];
    const float* Wq    = (const float*)d_in[4];
    const float* Wk    = (const float*)d_in[5];
    const float* Wv    = (const float*)d_in[6];
    const float* Wout  = (const float*)d_in[7];
    const float* b_out = (const float*)d_in[8];
    const int* is_causal = (const int*)d_in[9];
    float* out = (float*)d_out;

    cudaFuncSetAttribute(attn_mma_kernel,
                         cudaFuncAttributeMaxDynamicSharedMemorySize, ATTN_SMEM_BYTES);

    dim3 ggrid(DMODEL / 128, MROWS / 128);   // (8, 32)
    gemm_tc_kernel<<<ggrid, 256>>>(query, Wq, nullptr, nullptr, 0);
    gemm_tc_kernel<<<ggrid, 256>>>(key,   Wk, nullptr, nullptr, 1);
    gemm_tc_kernel<<<ggrid, 256>>>(value, Wv, nullptr, nullptr, 2);

    dim3 agrid(SEQ / 128, BATCH * NHEAD);    // (16, 32)
    attn_mma_kernel<<<agrid, 256, ATTN_SMEM_BYTES>>>(mask, is_causal);

    gemm_tc_kernel<<<ggrid, 256>>>(nullptr, Wout, b_out, out, 3);
}

// round 4
// speedup vs baseline: 4.4714x; 1.0473x over previous
#include <cuda_runtime.h>
#include <cstdint>

// Problem constants (fixed by the reference setup_inputs)
#define BATCH 2
#define SEQ   2048
#define DMODEL 1024
#define NHEAD 16
#define DK    64
#define MROWS (BATCH * SEQ)   // 4096

// Scratch: Q,K,V in [B,H,S,DK], O in [B,S,D]
__device__ float g_Q[BATCH * NHEAD * SEQ * DK];
__device__ float g_K[BATCH * NHEAD * SEQ * DK];
__device__ float g_V[BATCH * NHEAD * SEQ * DK];
__device__ float g_O[BATCH * SEQ * DMODEL];

// ---------------------------------------------------------------------------
// tf32 helpers (legacy mma.sync path, valid on sm_100a)
// ---------------------------------------------------------------------------
__device__ __forceinline__ unsigned f2tf32(float f) {
    unsigned u;
    asm("cvt.rna.tf32.f32 %0, %1;" : "=r"(u) : "f"(f));
    return u;
}

__device__ __forceinline__ void mma_tf32(float c[4], const unsigned a[4], const unsigned b[2]) {
    asm volatile(
        "mma.sync.aligned.m16n8k8.row.col.f32.tf32.tf32.f32 "
        "{%0,%1,%2,%3}, {%4,%5,%6,%7}, {%8,%9}, {%0,%1,%2,%3};\n"
        : "+f"(c[0]), "+f"(c[1]), "+f"(c[2]), "+f"(c[3])
        : "r"(a[0]), "r"(a[1]), "r"(a[2]), "r"(a[3]), "r"(b[0]), "r"(b[1]));
}

#define CP_ASYNC16(dst_u32, src) \
    asm volatile("cp.async.cg.shared.global [%0], [%1], 16;" :: "r"(dst_u32), "l"(src))
#define CP_COMMIT() asm volatile("cp.async.commit_group;")
#define CP_WAIT1()  asm volatile("cp.async.wait_group 1;")

// ---------------------------------------------------------------------------
// Tensor-core GEMM with 3xTF32 compensation (unchanged from R3).
// ---------------------------------------------------------------------------
#define TPAD 20

__global__ __launch_bounds__(256, 2) void gemm_tc_kernel(
    const float* __restrict__ A, const float* __restrict__ W,
    const float* __restrict__ bias, float* __restrict__ outFlat, int mode)
{
    __shared__ unsigned Ah[128][TPAD];
    __shared__ unsigned Al[128][TPAD];
    __shared__ unsigned Wh[128][TPAD];
    __shared__ unsigned Wl[128][TPAD];

    const float* Ap = (mode == 3) ? g_O : A;

    const int tid  = threadIdx.x;
    const int warp = tid >> 5;
    const int lane = tid & 31;
    const int g    = lane >> 2;
    const int tg   = lane & 3;
    const int wm   = warp >> 1;
    const int wn   = warp & 1;
    const int m0   = blockIdx.y << 7;
    const int n0   = blockIdx.x << 7;

    const int lr  = tid >> 2;
    const int lk4 = (tid & 3) << 2;

    float acc[2][8][4];
#pragma unroll
    for (int mf = 0; mf < 2; mf++)
#pragma unroll
        for (int nf = 0; nf < 8; nf++)
#pragma unroll
            for (int j = 0; j < 4; j++) acc[mf][nf][j] = 0.f;

    float4 aR[2], wR[2];
#pragma unroll
    for (int it = 0; it < 2; it++) {
        int r = lr + (it << 6);
        aR[it] = *(const float4*)&Ap[(m0 + r) * DMODEL + lk4];
        wR[it] = *(const float4*)&W[(n0 + r) * DMODEL + lk4];
    }

    for (int k0 = 0; k0 < DMODEL; k0 += 16) {
        __syncthreads();
#pragma unroll
        for (int it = 0; it < 2; it++) {
            int r = lr + (it << 6);
            const float* av = (const float*)&aR[it];
            const float* wv = (const float*)&wR[it];
            uint4 ahi, alo, whi, wlo;
            unsigned* ah = (unsigned*)&ahi; unsigned* al = (unsigned*)&alo;
            unsigned* wh = (unsigned*)&whi; unsigned* wl = (unsigned*)&wlo;
#pragma unroll
            for (int j = 0; j < 4; j++) {
                unsigned h = f2tf32(av[j]);
                ah[j] = h;
                al[j] = f2tf32(av[j] - __uint_as_float(h));
                unsigned h2 = f2tf32(wv[j]);
                wh[j] = h2;
                wl[j] = f2tf32(wv[j] - __uint_as_float(h2));
            }
            *(uint4*)&Ah[r][lk4] = ahi;
            *(uint4*)&Al[r][lk4] = alo;
            *(uint4*)&Wh[r][lk4] = whi;
            *(uint4*)&Wl[r][lk4] = wlo;
        }
        __syncthreads();

        if (k0 + 16 < DMODEL) {
#pragma unroll
            for (int it = 0; it < 2; it++) {
                int r = lr + (it << 6);
                aR[it] = *(const float4*)&Ap[(m0 + r) * DMODEL + k0 + 16 + lk4];
                wR[it] = *(const float4*)&W[(n0 + r) * DMODEL + k0 + 16 + lk4];
            }
        }

#pragma unroll
        for (int ks = 0; ks < 2; ks++) {
            const int kk = (ks << 3) + tg;
            unsigned ah[2][4], al[2][4];
#pragma unroll
            for (int mf = 0; mf < 2; mf++) {
                int r0 = (wm << 5) + (mf << 4) + g;
                ah[mf][0] = Ah[r0][kk];     ah[mf][1] = Ah[r0 + 8][kk];
                ah[mf][2] = Ah[r0][kk + 4]; ah[mf][3] = Ah[r0 + 8][kk + 4];
                al[mf][0] = Al[r0][kk];     al[mf][1] = Al[r0 + 8][kk];
                al[mf][2] = Al[r0][kk + 4]; al[mf][3] = Al[r0 + 8][kk + 4];
            }
#pragma unroll
            for (int nf = 0; nf < 8; nf++) {
                int nr = (wn << 6) + (nf << 3) + g;
                unsigned bh[2], bl[2];
                bh[0] = Wh[nr][kk]; bh[1] = Wh[nr][kk + 4];
                bl[0] = Wl[nr][kk]; bl[1] = Wl[nr][kk + 4];
#pragma unroll
                for (int mf = 0; mf < 2; mf++) {
                    mma_tf32(acc[mf][nf], ah[mf], bl);
                    mma_tf32(acc[mf][nf], al[mf], bh);
                    mma_tf32(acc[mf][nf], ah[mf], bh);
                }
            }
        }
    }

    if (mode == 3) {
#pragma unroll
        for (int mf = 0; mf < 2; mf++) {
            int r0 = m0 + (wm << 5) + (mf << 4) + g;
#pragma unroll
            for (int nf = 0; nf < 8; nf++) {
                int n = n0 + (wn << 6) + (nf << 3) + (tg << 1);
                float2 bi = *(const float2*)&bias[n];
                float2 w0, w1;
                w0.x = acc[mf][nf][0] + bi.x; w0.y = acc[mf][nf][1] + bi.y;
                w1.x = acc[mf][nf][2] + bi.x; w1.y = acc[mf][nf][3] + bi.y;
                *(float2*)&outFlat[r0 * DMODEL + n] = w0;
                *(float2*)&outFlat[(r0 + 8) * DMODEL + n] = w1;
            }
        }
    } else {
        float* outp = (mode == 0) ? g_Q : ((mode == 1) ? g_K : g_V);
#pragma unroll
        for (int mf = 0; mf < 2; mf++) {
            int m = m0 + (wm << 5) + (mf << 4) + g;
            int bb0 = m >> 11;
            int s   = m & 2047;
            int mb1 = m + 8;
            int bb1 = mb1 >> 11;
            int s1  = mb1 & 2047;
#pragma unroll
            for (int nf = 0; nf < 8; nf++) {
                int n = n0 + (wn << 6) + (nf << 3) + (tg << 1);
                int h = n >> 6;
                int d = n & 63;
                float2 w0, w1;
                w0.x = acc[mf][nf][0]; w0.y = acc[mf][nf][1];
                w1.x = acc[mf][nf][2]; w1.y = acc[mf][nf][3];
                *(float2*)&outp[(((bb0 << 4) + h) * SEQ + s) * DK + d] = w0;
                *(float2*)&outp[(((bb1 << 4) + h) * SEQ + s1) * DK + d] = w1;
            }
        }
    }
}

// ---------------------------------------------------------------------------
// Flash attention, tf32 mma.sync, cp.async double-buffered K/V (raw fp32 in
// smem, tf32 convert at fragment load), mask prefetch, 2 CTAs/SM target.
// smem: QP (tf32 Q then P) [128][72]; K fp32 2x[64][68]; V fp32 2x[64][72].
// Total 108544 B.
// ---------------------------------------------------------------------------
#define AQP_ST 72
#define AK_ST  68
#define AV_ST  72
#define KBUF_W (64 * AK_ST)
#define VBUF_W (64 * AV_ST)
#define ATTN_SMEM_BYTES ((128 * AQP_ST + 2 * KBUF_W + 2 * VBUF_W) * 4)  // 108544

__global__ __launch_bounds__(256, 2) void attn_mma_kernel(
    const unsigned char* __restrict__ mask, const int* __restrict__ is_causal_p)
{
    extern __shared__ float smf[];
    unsigned* QPs = (unsigned*)smf;                 // [128][72]
    float* Kbuf = smf + 128 * AQP_ST;               // 2 x [64][68]
    float* Vbuf = Kbuf + 2 * KBUF_W;                // 2 x [64][72]

    const int bh = blockIdx.y;
    const int qt = blockIdx.x;
    const int b  = bh >> 4;
    const int h  = bh & 15;
    const int causal = is_causal_p[0];
    const int q0 = qt << 7;

    const int tid  = threadIdx.x;
    const int warp = tid >> 5;
    const int lane = tid & 31;
    const int g    = lane >> 2;
    const int tg   = lane & 3;

    const float* Qg = g_Q + ((size_t)bh * SEQ + q0) * DK;
    const float* Kg = g_K + (size_t)bh * SEQ * DK;
    const float* Vg = g_V + (size_t)bh * SEQ * DK;

    // loader mapping (shared by Q store and KV cp.async)
    const int lrow = tid >> 4;              // 0..15 (row block), full row via +16*it
    const int lc4  = (tid & 15) << 2;       // word col 0,4,..,60

    // ---- Load Q tile (128 x 64) to smem as tf32 ----
#pragma unroll
    for (int it = 0; it < 8; it++) {
        int r = lrow + (it << 4);
        float4 v = *(const float4*)&Qg[r * DK + lc4];
        uint4 u;
        u.x = f2tf32(v.x); u.y = f2tf32(v.y);
        u.z = f2tf32(v.z); u.w = f2tf32(v.w);
        *(uint4*)&QPs[r * AQP_ST + lc4] = u;
    }

    // ---- issue cp.async for tile 0 into buffer 0 ----
    {
        const float* Kt = Kg;
        const float* Vt = Vg;
#pragma unroll
        for (int it = 0; it < 4; it++) {
            int r = lrow + (it << 4);
            unsigned kd = (unsigned)__cvta_generic_to_shared(&Kbuf[r * AK_ST + lc4]);
            CP_ASYNC16(kd, &Kt[r * DK + lc4]);
            unsigned vd = (unsigned)__cvta_generic_to_shared(&Vbuf[r * AV_ST + lc4]);
            CP_ASYNC16(vd, &Vt[r * DK + lc4]);
        }
    }
    CP_COMMIT();
    __syncthreads();   // Q visible CTA-wide

    // ---- Q fragments into registers ----
    const int r0 = (warp << 4) + g;
    const int r1 = r0 + 8;
    unsigned qf[8][4];
#pragma unroll
    for (int ks = 0; ks < 8; ks++) {
        int k = (ks << 3) + tg;
        qf[ks][0] = QPs[r0 * AQP_ST + k];
        qf[ks][1] = QPs[r1 * AQP_ST + k];
        qf[ks][2] = QPs[r0 * AQP_ST + k + 4];
        qf[ks][3] = QPs[r1 * AQP_ST + k + 4];
    }

    const int gr0 = q0 + r0;
    const int gr1 = q0 + r1;
    const unsigned char* mrow0 = mask + (size_t)b * SEQ * SEQ + (size_t)gr0 * SEQ;
    const unsigned char* mrow1 = mask + (size_t)b * SEQ * SEQ + (size_t)gr1 * SEQ;

    float m0 = -1e30f, m1 = -1e30f, l0 = 0.f, l1 = 0.f;
    float of[8][4];
#pragma unroll
    for (int nf = 0; nf < 8; nf++)
#pragma unroll
        for (int j = 0; j < 4; j++) of[nf][j] = 0.f;

    const int ntiles = causal ? (2 * qt + 2) : (SEQ / 64);
    const float scale = 0.125f;

    for (int t = 0; t < ntiles; t++) {
        const int k0 = t << 6;
        if (t > 0) __syncthreads();   // readers of the buffer we are about to fill are done

        // ---- prefetch tile t+1 into the other buffer ----
        if (t + 1 < ntiles) {
            const int nb = (t + 1) & 1;
            const float* Kt = Kg + ((t + 1) << 6) * DK;
            const float* Vt = Vg + ((t + 1) << 6) * DK;
            float* Kd = Kbuf + nb * KBUF_W;
            float* Vd = Vbuf + nb * VBUF_W;
#pragma unroll
            for (int it = 0; it < 4; it++) {
                int r = lrow + (it << 4);
                unsigned kd = (unsigned)__cvta_generic_to_shared(&Kd[r * AK_ST + lc4]);
                CP_ASYNC16(kd, &Kt[r * DK + lc4]);
                unsigned vd = (unsigned)__cvta_generic_to_shared(&Vd[r * AV_ST + lc4]);
                CP_ASYNC16(vd, &Vt[r * DK + lc4]);
            }
        }
        CP_COMMIT();
        CP_WAIT1();        // tile t's copies done (this thread)
        __syncthreads();   // visible CTA-wide

        const float* Kb = Kbuf + (t & 1) * KBUF_W;
        const float* Vb = Vbuf + (t & 1) * VBUF_W;

        // ---- mask prefetch (overlaps the QK^T MMAs below) ----
        uchar2 mA[8], mB[8];
#pragma unroll
        for (int nf = 0; nf < 8; nf++) {
            int col = k0 + (nf << 3) + (tg << 1);
            mA[nf] = *(const uchar2*)(mrow0 + col);
            mB[nf] = *(const uchar2*)(mrow1 + col);
        }

        // ---- S = Q @ K^T ----
        float s[8][4];
#pragma unroll
        for (int nf = 0; nf < 8; nf++)
#pragma unroll
            for (int j = 0; j < 4; j++) s[nf][j] = 0.f;

#pragma unroll
        for (int nf = 0; nf < 8; nf++) {
            int nrow = (nf << 3) + g;
#pragma unroll
            for (int ks = 0; ks < 8; ks++) {
                int k = (ks << 3) + tg;
                unsigned bb[2];
                bb[0] = f2tf32(Kb[nrow * AK_ST + k]);
                bb[1] = f2tf32(Kb[nrow * AK_ST + k + 4]);
                mma_tf32(s[nf], qf[ks], bb);
            }
        }

        // ---- scale + mask ----
#pragma unroll
        for (int nf = 0; nf < 8; nf++) {
            int col = k0 + (nf << 3) + (tg << 1);
            bool d00 = mA[nf].x || (causal && (col     > gr0));
            bool d01 = mA[nf].y || (causal && (col + 1 > gr0));
            bool d10 = mB[nf].x || (causal && (col     > gr1));
            bool d11 = mB[nf].y || (causal && (col + 1 > gr1));
            s[nf][0] = d00 ? -1e30f : s[nf][0] * scale;
            s[nf][1] = d01 ? -1e30f : s[nf][1] * scale;
            s[nf][2] = d10 ? -1e30f : s[nf][2] * scale;
            s[nf][3] = d11 ? -1e30f : s[nf][3] * scale;
        }

        // ---- online softmax ----
        float mx0 = -1e30f, mx1 = -1e30f;
#pragma unroll
        for (int nf = 0; nf < 8; nf++) {
            mx0 = fmaxf(mx0, fmaxf(s[nf][0], s[nf][1]));
            mx1 = fmaxf(mx1, fmaxf(s[nf][2], s[nf][3]));
        }
        mx0 = fmaxf(mx0, __shfl_xor_sync(0xffffffffu, mx0, 1));
        mx0 = fmaxf(mx0, __shfl_xor_sync(0xffffffffu, mx0, 2));
        mx1 = fmaxf(mx1, __shfl_xor_sync(0xffffffffu, mx1, 1));
        mx1 = fmaxf(mx1, __shfl_xor_sync(0xffffffffu, mx1, 2));
        float m0n = fmaxf(m0, mx0);
        float m1n = fmaxf(m1, mx1);
        float sf0 = __expf(m0 - m0n);
        float sf1 = __expf(m1 - m1n);
        float rs0 = 0.f, rs1 = 0.f;
#pragma unroll
        for (int nf = 0; nf < 8; nf++) {
            float p0 = __expf(s[nf][0] - m0n);
            float p1 = __expf(s[nf][1] - m0n);
            float p2 = __expf(s[nf][2] - m1n);
            float p3 = __expf(s[nf][3] - m1n);
            s[nf][0] = p0; s[nf][1] = p1; s[nf][2] = p2; s[nf][3] = p3;
            rs0 += p0 + p1;
            rs1 += p2 + p3;
        }
        rs0 += __shfl_xor_sync(0xffffffffu, rs0, 1);
        rs0 += __shfl_xor_sync(0xffffffffu, rs0, 2);
        rs1 += __shfl_xor_sync(0xffffffffu, rs1, 1);
        rs1 += __shfl_xor_sync(0xffffffffu, rs1, 2);
        l0 = l0 * sf0 + rs0;
        l1 = l1 * sf1 + rs1;
        m0 = m0n; m1 = m1n;
#pragma unroll
        for (int nf = 0; nf < 8; nf++) {
            of[nf][0] *= sf0; of[nf][1] *= sf0;
            of[nf][2] *= sf1; of[nf][3] *= sf1;
        }

        // ---- write P (tf32) to warp-local rows of QPs ----
#pragma unroll
        for (int nf = 0; nf < 8; nf++) {
            int c = (nf << 3) + (tg << 1);
            uint2 p0; p0.x = f2tf32(s[nf][0]); p0.y = f2tf32(s[nf][1]);
            uint2 p1; p1.x = f2tf32(s[nf][2]); p1.y = f2tf32(s[nf][3]);
            *(uint2*)&QPs[r0 * AQP_ST + c] = p0;
            *(uint2*)&QPs[r1 * AQP_ST + c] = p1;
        }
        __syncwarp();

        // ---- O += P @ V ----
#pragma unroll
        for (int ks = 0; ks < 8; ks++) {
            unsigned a[4];
            int k = (ks << 3) + tg;
            a[0] = QPs[r0 * AQP_ST + k];
            a[1] = QPs[r1 * AQP_ST + k];
            a[2] = QPs[r0 * AQP_ST + k + 4];
            a[3] = QPs[r1 * AQP_ST + k + 4];
#pragma unroll
            for (int nf = 0; nf < 8; nf++) {
                int n = (nf << 3) + g;
                unsigned bb[2];
                bb[0] = f2tf32(Vb[((ks << 3) + tg) * AV_ST + n]);
                bb[1] = f2tf32(Vb[((ks << 3) + tg + 4) * AV_ST + n]);
                mma_tf32(of[nf], a, bb);
            }
        }
        __syncwarp();
    }

    // ---- epilogue ----
    float inv0 = (m0 > -1e29f && l0 > 0.f) ? (1.f / l0) : 0.f;
    float inv1 = (m1 > -1e29f && l1 > 0.f) ? (1.f / l1) : 0.f;
    float* Og0 = g_O + ((size_t)b * SEQ + gr0) * DMODEL + (h << 6);
    float* Og1 = g_O + ((size_t)b * SEQ + gr1) * DMODEL + (h << 6);
#pragma unroll
    for (int nf = 0; nf < 8; nf++) {
        int c = (nf << 3) + (tg << 1);
        float2 w0; w0.x = of[nf][0] * inv0; w0.y = of[nf][1] * inv0;
        float2 w1; w1.x = of[nf][2] * inv1; w1.y = of[nf][3] * inv1;
        *(float2*)&Og0[c] = w0;
        *(float2*)&Og1[c] = w1;
    }
}

// ---------------------------------------------------------------------------
extern "C" void kernel_launch(void* const* d_in, const int* in_sizes, int n_in,
                              void* d_out, int out_size)
{
    const float* query = (const float*)d_in[0];
    const float* key   = (const float*)d_in[1];
    const float* value = (const float*)d_in[2];
    const unsigned char* mask = (const unsigned char*)d_in[3];
    const float* Wq    = (const float*)d_in[4];
    const float* Wk    = (const float*)d_in[5];
    const float* Wv    = (const float*)d_in[6];
    const float* Wout  = (const float*)d_in[7];
    const float* b_out = (const float*)d_in[8];
    const int* is_causal = (const int*)d_in[9];
    float* out = (float*)d_out;

    cudaFuncSetAttribute(attn_mma_kernel,
                         cudaFuncAttributeMaxDynamicSharedMemorySize, ATTN_SMEM_BYTES);

    dim3 ggrid(DMODEL / 128, MROWS / 128);   // (8, 32)
    gemm_tc_kernel<<<ggrid, 256>>>(query, Wq, nullptr, nullptr, 0);
    gemm_tc_kernel<<<ggrid, 256>>>(key,   Wk, nullptr, nullptr, 1);
    gemm_tc_kernel<<<ggrid, 256>>>(value, Wv, nullptr, nullptr, 2);

    dim3 agrid(SEQ / 128, BATCH * NHEAD);    // (16, 32)
    attn_mma_kernel<<<agrid, 256, ATTN_SMEM_BYTES>>>(mask, is_causal);

    gemm_tc_kernel<<<ggrid, 256>>>(nullptr, Wout, b_out, out, 3);
}

// round 5
// speedup vs baseline: 4.9653x; 1.1105x over previous
#include <cuda_runtime.h>
#include <cstdint>

// Problem constants (fixed by the reference setup_inputs)
#define BATCH 2
#define SEQ   2048
#define DMODEL 1024
#define NHEAD 16
#define DK    64
#define MROWS (BATCH * SEQ)   // 4096

// Scratch: Q,K,V in [B,H,S,DK] (tf32-rounded floats), O in [B,S,D]
__device__ float g_Q[BATCH * NHEAD * SEQ * DK];
__device__ float g_K[BATCH * NHEAD * SEQ * DK];
__device__ float g_V[BATCH * NHEAD * SEQ * DK];
__device__ float g_O[BATCH * SEQ * DMODEL];

// ---------------------------------------------------------------------------
// tf32 helpers (legacy mma.sync path, valid on sm_100a)
// ---------------------------------------------------------------------------
__device__ __forceinline__ unsigned f2tf32(float f) {
    unsigned u;
    asm("cvt.rna.tf32.f32 %0, %1;" : "=r"(u) : "f"(f));
    return u;
}

__device__ __forceinline__ void mma_tf32(float c[4], const unsigned a[4], const unsigned b[2]) {
    asm volatile(
        "mma.sync.aligned.m16n8k8.row.col.f32.tf32.tf32.f32 "
        "{%0,%1,%2,%3}, {%4,%5,%6,%7}, {%8,%9}, {%0,%1,%2,%3};\n"
        : "+f"(c[0]), "+f"(c[1]), "+f"(c[2]), "+f"(c[3])
        : "r"(a[0]), "r"(a[1]), "r"(a[2]), "r"(a[3]), "r"(b[0]), "r"(b[1]));
}

#define CP_ASYNC16(dst_u32, src) \
    asm volatile("cp.async.cg.shared.global [%0], [%1], 16;" :: "r"(dst_u32), "l"(src))
#define CP_COMMIT() asm volatile("cp.async.commit_group;")
#define CP_WAIT1()  asm volatile("cp.async.wait_group 1;")

// ---------------------------------------------------------------------------
// Tensor-core GEMM core with 3xTF32 compensation.
// C[M,N] = A[M,K] @ W[N,K]^T.  M=4096, N=1024, K=1024.
// CTA 128x128, K-chunk 16, 8 warps (4M x 2N), warp tile 32x64.
// ---------------------------------------------------------------------------
#define TPAD 20

struct GemmSmem {
    unsigned Ah[128][TPAD];
    unsigned Al[128][TPAD];
    unsigned Wh[128][TPAD];
    unsigned Wl[128][TPAD];
};

// Computes the accumulators for this CTA; caller handles the epilogue.
__device__ __forceinline__ void gemm_core(
    const float* __restrict__ Ap, const float* __restrict__ W,
    int m0, int n0, float acc[2][8][4])
{
    __shared__ GemmSmem sm;

    const int tid  = threadIdx.x;
    const int warp = tid >> 5;
    const int lane = tid & 31;
    const int g    = lane >> 2;
    const int tg   = lane & 3;
    const int wm   = warp >> 1;
    const int wn   = warp & 1;

    const int lr  = tid >> 2;
    const int lk4 = (tid & 3) << 2;

#pragma unroll
    for (int mf = 0; mf < 2; mf++)
#pragma unroll
        for (int nf = 0; nf < 8; nf++)
#pragma unroll
            for (int j = 0; j < 4; j++) acc[mf][nf][j] = 0.f;

    float4 aR[2], wR[2];
#pragma unroll
    for (int it = 0; it < 2; it++) {
        int r = lr + (it << 6);
        aR[it] = *(const float4*)&Ap[(m0 + r) * DMODEL + lk4];
        wR[it] = *(const float4*)&W[(n0 + r) * DMODEL + lk4];
    }

    for (int k0 = 0; k0 < DMODEL; k0 += 16) {
        __syncthreads();
#pragma unroll
        for (int it = 0; it < 2; it++) {
            int r = lr + (it << 6);
            const float* av = (const float*)&aR[it];
            const float* wv = (const float*)&wR[it];
            uint4 ahi, alo, whi, wlo;
            unsigned* ah = (unsigned*)&ahi; unsigned* al = (unsigned*)&alo;
            unsigned* wh = (unsigned*)&whi; unsigned* wl = (unsigned*)&wlo;
#pragma unroll
            for (int j = 0; j < 4; j++) {
                unsigned hh = f2tf32(av[j]);
                ah[j] = hh;
                al[j] = f2tf32(av[j] - __uint_as_float(hh));
                unsigned h2 = f2tf32(wv[j]);
                wh[j] = h2;
                wl[j] = f2tf32(wv[j] - __uint_as_float(h2));
            }
            *(uint4*)&sm.Ah[r][lk4] = ahi;
            *(uint4*)&sm.Al[r][lk4] = alo;
            *(uint4*)&sm.Wh[r][lk4] = whi;
            *(uint4*)&sm.Wl[r][lk4] = wlo;
        }
        __syncthreads();

        if (k0 + 16 < DMODEL) {
#pragma unroll
            for (int it = 0; it < 2; it++) {
                int r = lr + (it << 6);
                aR[it] = *(const float4*)&Ap[(m0 + r) * DMODEL + k0 + 16 + lk4];
                wR[it] = *(const float4*)&W[(n0 + r) * DMODEL + k0 + 16 + lk4];
            }
        }

#pragma unroll
        for (int ks = 0; ks < 2; ks++) {
            const int kk = (ks << 3) + tg;
            unsigned ah[2][4], al[2][4];
#pragma unroll
            for (int mf = 0; mf < 2; mf++) {
                int r0 = (wm << 5) + (mf << 4) + g;
                ah[mf][0] = sm.Ah[r0][kk];     ah[mf][1] = sm.Ah[r0 + 8][kk];
                ah[mf][2] = sm.Ah[r0][kk + 4]; ah[mf][3] = sm.Ah[r0 + 8][kk + 4];
                al[mf][0] = sm.Al[r0][kk];     al[mf][1] = sm.Al[r0 + 8][kk];
                al[mf][2] = sm.Al[r0][kk + 4]; al[mf][3] = sm.Al[r0 + 8][kk + 4];
            }
#pragma unroll
            for (int nf = 0; nf < 8; nf++) {
                int nr = (wn << 6) + (nf << 3) + g;
                unsigned bh[2], bl[2];
                bh[0] = sm.Wh[nr][kk]; bh[1] = sm.Wh[nr][kk + 4];
                bl[0] = sm.Wl[nr][kk]; bl[1] = sm.Wl[nr][kk + 4];
#pragma unroll
                for (int mf = 0; mf < 2; mf++) {
                    mma_tf32(acc[mf][nf], ah[mf], bl);
                    mma_tf32(acc[mf][nf], al[mf], bh);
                    mma_tf32(acc[mf][nf], ah[mf], bh);
                }
            }
        }
    }
}

// ---- fused Q/K/V projections: blockIdx.z selects the GEMM.
// Outputs are rounded to tf32 so the attention kernel needs NO cvt. ----
__global__ __launch_bounds__(256, 2) void gemm_qkv_kernel(
    const float* __restrict__ query, const float* __restrict__ key,
    const float* __restrict__ value, const float* __restrict__ Wq,
    const float* __restrict__ Wk, const float* __restrict__ Wv)
{
    const int z = blockIdx.z;
    const float* Ap = (z == 0) ? query : ((z == 1) ? key : value);
    const float* W  = (z == 0) ? Wq    : ((z == 1) ? Wk  : Wv);
    float* outp     = (z == 0) ? g_Q   : ((z == 1) ? g_K : g_V);

    const int m0 = blockIdx.y << 7;
    const int n0 = blockIdx.x << 7;

    float acc[2][8][4];
    gemm_core(Ap, W, m0, n0, acc);

    const int tid  = threadIdx.x;
    const int warp = tid >> 5;
    const int lane = tid & 31;
    const int g    = lane >> 2;
    const int tg   = lane & 3;
    const int wm   = warp >> 1;
    const int wn   = warp & 1;

#pragma unroll
    for (int mf = 0; mf < 2; mf++) {
        int m = m0 + (wm << 5) + (mf << 4) + g;
        int bb0 = m >> 11;
        int s   = m & 2047;
        int mb1 = m + 8;
        int bb1 = mb1 >> 11;
        int s1  = mb1 & 2047;
#pragma unroll
        for (int nf = 0; nf < 8; nf++) {
            int n = n0 + (wn << 6) + (nf << 3) + (tg << 1);
            int h = n >> 6;
            int d = n & 63;
            float2 w0, w1;
            w0.x = __uint_as_float(f2tf32(acc[mf][nf][0]));
            w0.y = __uint_as_float(f2tf32(acc[mf][nf][1]));
            w1.x = __uint_as_float(f2tf32(acc[mf][nf][2]));
            w1.y = __uint_as_float(f2tf32(acc[mf][nf][3]));
            *(float2*)&outp[(((bb0 << 4) + h) * SEQ + s) * DK + d] = w0;
            *(float2*)&outp[(((bb1 << 4) + h) * SEQ + s1) * DK + d] = w1;
        }
    }
}

// ---- output projection: C = g_O @ Wout^T + bias ----
__global__ __launch_bounds__(256, 2) void gemm_out_kernel(
    const float* __restrict__ Wout, const float* __restrict__ bias,
    float* __restrict__ outFlat)
{
    const int m0 = blockIdx.y << 7;
    const int n0 = blockIdx.x << 7;

    float acc[2][8][4];
    gemm_core(g_O, Wout, m0, n0, acc);

    const int tid  = threadIdx.x;
    const int warp = tid >> 5;
    const int lane = tid & 31;
    const int g    = lane >> 2;
    const int tg   = lane & 3;
    const int wm   = warp >> 1;
    const int wn   = warp & 1;

#pragma unroll
    for (int mf = 0; mf < 2; mf++) {
        int r0 = m0 + (wm << 5) + (mf << 4) + g;
#pragma unroll
        for (int nf = 0; nf < 8; nf++) {
            int n = n0 + (wn << 6) + (nf << 3) + (tg << 1);
            float2 bi = *(const float2*)&bias[n];
            float2 w0, w1;
            w0.x = acc[mf][nf][0] + bi.x; w0.y = acc[mf][nf][1] + bi.y;
            w1.x = acc[mf][nf][2] + bi.x; w1.y = acc[mf][nf][3] + bi.y;
            *(float2*)&outFlat[r0 * DMODEL + n] = w0;
            *(float2*)&outFlat[(r0 + 8) * DMODEL + n] = w1;
        }
    }
}

// ---------------------------------------------------------------------------
// Flash attention, tf32 mma.sync, cp.async double-buffered K/V.
// g_Q/g_K/g_V hold tf32-rounded floats -> NO cvt needed in inner loops:
// smem words feed the MMA directly as bit patterns.
// ---------------------------------------------------------------------------
#define AQP_ST 72
#define AK_ST  68
#define AV_ST  72
#define KBUF_W (64 * AK_ST)
#define VBUF_W (64 * AV_ST)
#define ATTN_SMEM_BYTES ((128 * AQP_ST + 2 * KBUF_W + 2 * VBUF_W) * 4)  // 108544

__global__ __launch_bounds__(256, 2) void attn_mma_kernel(
    const unsigned char* __restrict__ mask, const int* __restrict__ is_causal_p)
{
    extern __shared__ unsigned smu[];
    unsigned* QPs  = smu;                       // [128][72]
    unsigned* Kbuf = smu + 128 * AQP_ST;        // 2 x [64][68]
    unsigned* Vbuf = Kbuf + 2 * KBUF_W;         // 2 x [64][72]

    const int bh = blockIdx.y;
    const int qt = gridDim.x - 1 - blockIdx.x;  // heavy (large-ntiles) CTAs first
    const int b  = bh >> 4;
    const int h  = bh & 15;
    const int causal = is_causal_p[0];
    const int q0 = qt << 7;

    const int tid  = threadIdx.x;
    const int warp = tid >> 5;
    const int lane = tid & 31;
    const int g    = lane >> 2;
    const int tg   = lane & 3;

    const float* Qg = g_Q + ((size_t)bh * SEQ + q0) * DK;
    const float* Kg = g_K + (size_t)bh * SEQ * DK;
    const float* Vg = g_V + (size_t)bh * SEQ * DK;

    const int lrow = tid >> 4;              // 0..15
    const int lc4  = (tid & 15) << 2;       // 0,4,..,60

    // ---- Load Q tile (already tf32-valued): plain copy ----
#pragma unroll
    for (int it = 0; it < 8; it++) {
        int r = lrow + (it << 4);
        *(uint4*)&QPs[r * AQP_ST + lc4] = *(const uint4*)&Qg[r * DK + lc4];
    }

    // ---- cp.async tile 0 into buffer 0 ----
#pragma unroll
    for (int it = 0; it < 4; it++) {
        int r = lrow + (it << 4);
        unsigned kd = (unsigned)__cvta_generic_to_shared(&Kbuf[r * AK_ST + lc4]);
        CP_ASYNC16(kd, &Kg[r * DK + lc4]);
        unsigned vd = (unsigned)__cvta_generic_to_shared(&Vbuf[r * AV_ST + lc4]);
        CP_ASYNC16(vd, &Vg[r * DK + lc4]);
    }
    CP_COMMIT();
    __syncthreads();

    // ---- Q fragments ----
    const int r0 = (warp << 4) + g;
    const int r1 = r0 + 8;
    unsigned qf[8][4];
#pragma unroll
    for (int ks = 0; ks < 8; ks++) {
        int k = (ks << 3) + tg;
        qf[ks][0] = QPs[r0 * AQP_ST + k];
        qf[ks][1] = QPs[r1 * AQP_ST + k];
        qf[ks][2] = QPs[r0 * AQP_ST + k + 4];
        qf[ks][3] = QPs[r1 * AQP_ST + k + 4];
    }

    const int gr0 = q0 + r0;
    const int gr1 = q0 + r1;
    const unsigned char* mrow0 = mask + (size_t)b * SEQ * SEQ + (size_t)gr0 * SEQ;
    const unsigned char* mrow1 = mask + (size_t)b * SEQ * SEQ + (size_t)gr1 * SEQ;

    float m0 = -1e30f, m1 = -1e30f, l0 = 0.f, l1 = 0.f;
    float of[8][4];
#pragma unroll
    for (int nf = 0; nf < 8; nf++)
#pragma unroll
        for (int j = 0; j < 4; j++) of[nf][j] = 0.f;

    const int ntiles = causal ? (2 * qt + 2) : (SEQ / 64);
    const float scale = 0.125f;

    for (int t = 0; t < ntiles; t++) {
        const int k0 = t << 6;
        if (t > 0) __syncthreads();

        if (t + 1 < ntiles) {
            const int nb = (t + 1) & 1;
            const float* Kt = Kg + ((t + 1) << 6) * DK;
            const float* Vt = Vg + ((t + 1) << 6) * DK;
            unsigned* Kd = Kbuf + nb * KBUF_W;
            unsigned* Vd = Vbuf + nb * VBUF_W;
#pragma unroll
            for (int it = 0; it < 4; it++) {
                int r = lrow + (it << 4);
                unsigned kd = (unsigned)__cvta_generic_to_shared(&Kd[r * AK_ST + lc4]);
                CP_ASYNC16(kd, &Kt[r * DK + lc4]);
                unsigned vd = (unsigned)__cvta_generic_to_shared(&Vd[r * AV_ST + lc4]);
                CP_ASYNC16(vd, &Vt[r * DK + lc4]);
            }
        }
        CP_COMMIT();
        CP_WAIT1();
        __syncthreads();

        const unsigned* Kb = Kbuf + (t & 1) * KBUF_W;
        const unsigned* Vb = Vbuf + (t & 1) * VBUF_W;

        // ---- mask prefetch ----
        uchar2 mA[8], mB[8];
#pragma unroll
        for (int nf = 0; nf < 8; nf++) {
            int col = k0 + (nf << 3) + (tg << 1);
            mA[nf] = *(const uchar2*)(mrow0 + col);
            mB[nf] = *(const uchar2*)(mrow1 + col);
        }

        // ---- S = Q @ K^T (no cvt: bits already tf32) ----
        float s[8][4];
#pragma unroll
        for (int nf = 0; nf < 8; nf++)
#pragma unroll
            for (int j = 0; j < 4; j++) s[nf][j] = 0.f;

#pragma unroll
        for (int nf = 0; nf < 8; nf++) {
            int nrow = (nf << 3) + g;
#pragma unroll
            for (int ks = 0; ks < 8; ks++) {
                int k = (ks << 3) + tg;
                unsigned bb[2];
                bb[0] = Kb[nrow * AK_ST + k];
                bb[1] = Kb[nrow * AK_ST + k + 4];
                mma_tf32(s[nf], qf[ks], bb);
            }
        }

        // ---- scale + mask ----
#pragma unroll
        for (int nf = 0; nf < 8; nf++) {
            int col = k0 + (nf << 3) + (tg << 1);
            bool d00 = mA[nf].x || (causal && (col     > gr0));
            bool d01 = mA[nf].y || (causal && (col + 1 > gr0));
            bool d10 = mB[nf].x || (causal && (col     > gr1));
            bool d11 = mB[nf].y || (causal && (col + 1 > gr1));
            s[nf][0] = d00 ? -1e30f : s[nf][0] * scale;
            s[nf][1] = d01 ? -1e30f : s[nf][1] * scale;
            s[nf][2] = d10 ? -1e30f : s[nf][2] * scale;
            s[nf][3] = d11 ? -1e30f : s[nf][3] * scale;
        }

        // ---- online softmax ----
        float mx0 = -1e30f, mx1 = -1e30f;
#pragma unroll
        for (int nf = 0; nf < 8; nf++) {
            mx0 = fmaxf(mx0, fmaxf(s[nf][0], s[nf][1]));
            mx1 = fmaxf(mx1, fmaxf(s[nf][2], s[nf][3]));
        }
        mx0 = fmaxf(mx0, __shfl_xor_sync(0xffffffffu, mx0, 1));
        mx0 = fmaxf(mx0, __shfl_xor_sync(0xffffffffu, mx0, 2));
        mx1 = fmaxf(mx1, __shfl_xor_sync(0xffffffffu, mx1, 1));
        mx1 = fmaxf(mx1, __shfl_xor_sync(0xffffffffu, mx1, 2));
        float m0n = fmaxf(m0, mx0);
        float m1n = fmaxf(m1, mx1);
        float sf0 = __expf(m0 - m0n);
        float sf1 = __expf(m1 - m1n);
        float rs0 = 0.f, rs1 = 0.f;
#pragma unroll
        for (int nf = 0; nf < 8; nf++) {
            float p0 = __expf(s[nf][0] - m0n);
            float p1 = __expf(s[nf][1] - m0n);
            float p2 = __expf(s[nf][2] - m1n);
            float p3 = __expf(s[nf][3] - m1n);
            s[nf][0] = p0; s[nf][1] = p1; s[nf][2] = p2; s[nf][3] = p3;
            rs0 += p0 + p1;
            rs1 += p2 + p3;
        }
        rs0 += __shfl_xor_sync(0xffffffffu, rs0, 1);
        rs0 += __shfl_xor_sync(0xffffffffu, rs0, 2);
        rs1 += __shfl_xor_sync(0xffffffffu, rs1, 1);
        rs1 += __shfl_xor_sync(0xffffffffu, rs1, 2);
        l0 = l0 * sf0 + rs0;
        l1 = l1 * sf1 + rs1;
        m0 = m0n; m1 = m1n;
#pragma unroll
        for (int nf = 0; nf < 8; nf++) {
            of[nf][0] *= sf0; of[nf][1] *= sf0;
            of[nf][2] *= sf1; of[nf][3] *= sf1;
        }

        // ---- write P (tf32) to warp-local rows of QPs ----
#pragma unroll
        for (int nf = 0; nf < 8; nf++) {
            int c = (nf << 3) + (tg << 1);
            uint2 p0; p0.x = f2tf32(s[nf][0]); p0.y = f2tf32(s[nf][1]);
            uint2 p1; p1.x = f2tf32(s[nf][2]); p1.y = f2tf32(s[nf][3]);
            *(uint2*)&QPs[r0 * AQP_ST + c] = p0;
            *(uint2*)&QPs[r1 * AQP_ST + c] = p1;
        }
        __syncwarp();

        // ---- O += P @ V ----
#pragma unroll
        for (int ks = 0; ks < 8; ks++) {
            unsigned a[4];
            int k = (ks << 3) + tg;
            a[0] = QPs[r0 * AQP_ST + k];
            a[1] = QPs[r1 * AQP_ST + k];
            a[2] = QPs[r0 * AQP_ST + k + 4];
            a[3] = QPs[r1 * AQP_ST + k + 4];
#pragma unroll
            for (int nf = 0; nf < 8; nf++) {
                int n = (nf << 3) + g;
                unsigned bb[2];
                bb[0] = Vb[((ks << 3) + tg) * AV_ST + n];
                bb[1] = Vb[((ks << 3) + tg + 4) * AV_ST + n];
                mma_tf32(of[nf], a, bb);
            }
        }
        __syncwarp();
    }

    // ---- epilogue ----
    float inv0 = (m0 > -1e29f && l0 > 0.f) ? (1.f / l0) : 0.f;
    float inv1 = (m1 > -1e29f && l1 > 0.f) ? (1.f / l1) : 0.f;
    float* Og0 = g_O + ((size_t)b * SEQ + gr0) * DMODEL + (h << 6);
    float* Og1 = g_O + ((size_t)b * SEQ + gr1) * DMODEL + (h << 6);
#pragma unroll
    for (int nf = 0; nf < 8; nf++) {
        int c = (nf << 3) + (tg << 1);
        float2 w0; w0.x = of[nf][0] * inv0; w0.y = of[nf][1] * inv0;
        float2 w1; w1.x = of[nf][2] * inv1; w1.y = of[nf][3] * inv1;
        *(float2*)&Og0[c] = w0;
        *(float2*)&Og1[c] = w1;
    }
}

// ---------------------------------------------------------------------------
extern "C" void kernel_launch(void* const* d_in, const int* in_sizes, int n_in,
                              void* d_out, int out_size)
{
    const float* query = (const float*)d_in[0];
    const float* key   = (const float*)d_in[1];
    const float* value = (const float*)d_in[2];
    const unsigned char* mask = (const unsigned char*)d_in[3];
    const float* Wq    = (const float*)d_in[4];
    const float* Wk    = (const float*)d_in[5];
    const float* Wv    = (const float*)d_in[6];
    const float* Wout  = (const float*)d_in[7];
    const float* b_out = (const float*)d_in[8];
    const int* is_causal = (const int*)d_in[9];
    float* out = (float*)d_out;

    cudaFuncSetAttribute(attn_mma_kernel,
                         cudaFuncAttributeMaxDynamicSharedMemorySize, ATTN_SMEM_BYTES);

    dim3 qkvgrid(DMODEL / 128, MROWS / 128, 3);   // (8, 32, 3)
    gemm_qkv_kernel<<<qkvgrid, 256>>>(query, key, value, Wq, Wk, Wv);

    dim3 agrid(SEQ / 128, BATCH * NHEAD);         // (16, 32)
    attn_mma_kernel<<<agrid, 256, ATTN_SMEM_BYTES>>>(mask, is_causal);

    dim3 ogrid(DMODEL / 128, MROWS / 128);        // (8, 32)
    gemm_out_kernel<<<ogrid, 256>>>(Wout, b_out, out);
}

// round 6
// speedup vs baseline: 6.1925x; 1.2472x over previous
#include <cuda_runtime.h>
#include <cstdint>

// Problem constants (fixed by the reference setup_inputs)
#define BATCH 2
#define SEQ   2048
#define DMODEL 1024
#define NHEAD 16
#define DK    64
#define MROWS (BATCH * SEQ)   // 4096

// Scratch: Q,K,V in [B,H,S,DK] (tf32-rounded floats), O in [B,S,D]
__device__ float g_Q[BATCH * NHEAD * SEQ * DK];
__device__ float g_K[BATCH * NHEAD * SEQ * DK];
__device__ float g_V[BATCH * NHEAD * SEQ * DK];
__device__ float g_O[BATCH * SEQ * DMODEL];

// ---------------------------------------------------------------------------
// tf32 helpers (legacy mma.sync path, valid on sm_100a)
// ---------------------------------------------------------------------------
__device__ __forceinline__ unsigned f2tf32(float f) {
    unsigned u;
    asm("cvt.rna.tf32.f32 %0, %1;" : "=r"(u) : "f"(f));
    return u;
}

__device__ __forceinline__ void mma_tf32(float c[4], const unsigned a[4], const unsigned b[2]) {
    asm volatile(
        "mma.sync.aligned.m16n8k8.row.col.f32.tf32.tf32.f32 "
        "{%0,%1,%2,%3}, {%4,%5,%6,%7}, {%8,%9}, {%0,%1,%2,%3};\n"
        : "+f"(c[0]), "+f"(c[1]), "+f"(c[2]), "+f"(c[3])
        : "r"(a[0]), "r"(a[1]), "r"(a[2]), "r"(a[3]), "r"(b[0]), "r"(b[1]));
}

#define CP_ASYNC16(dst_u32, src) \
    asm volatile("cp.async.cg.shared.global [%0], [%1], 16;" :: "r"(dst_u32), "l"(src))
#define CP_COMMIT() asm volatile("cp.async.commit_group;")
#define CP_WAIT1()  asm volatile("cp.async.wait_group 1;")

// ---------------------------------------------------------------------------
// Tensor-core GEMM core with 2xTF32 compensation:
//   C = (a_hi + a_lo) * b_hi  (error = a * b_lo ~ 2^-12 relative)
// C[M,N] = A[M,K] @ W[N,K]^T.  M=4096, N=1024, K=1024.
// CTA 128x128, K-chunk 16, 8 warps (4M x 2N), warp tile 32x64.
// ---------------------------------------------------------------------------
#define TPAD 20

struct GemmSmem {
    unsigned Ah[128][TPAD];
    unsigned Al[128][TPAD];
    unsigned Wh[128][TPAD];
};

// Computes the accumulators for this CTA; caller handles the epilogue.
__device__ __forceinline__ void gemm_core(
    const float* __restrict__ Ap, const float* __restrict__ W,
    int m0, int n0, float acc[2][8][4])
{
    __shared__ GemmSmem sm;

    const int tid  = threadIdx.x;
    const int warp = tid >> 5;
    const int lane = tid & 31;
    const int g    = lane >> 2;
    const int tg   = lane & 3;
    const int wm   = warp >> 1;
    const int wn   = warp & 1;

    const int lr  = tid >> 2;
    const int lk4 = (tid & 3) << 2;

#pragma unroll
    for (int mf = 0; mf < 2; mf++)
#pragma unroll
        for (int nf = 0; nf < 8; nf++)
#pragma unroll
            for (int j = 0; j < 4; j++) acc[mf][nf][j] = 0.f;

    float4 aR[2], wR[2];
#pragma unroll
    for (int it = 0; it < 2; it++) {
        int r = lr + (it << 6);
        aR[it] = *(const float4*)&Ap[(m0 + r) * DMODEL + lk4];
        wR[it] = *(const float4*)&W[(n0 + r) * DMODEL + lk4];
    }

    for (int k0 = 0; k0 < DMODEL; k0 += 16) {
        __syncthreads();
#pragma unroll
        for (int it = 0; it < 2; it++) {
            int r = lr + (it << 6);
            const float* av = (const float*)&aR[it];
            const float* wv = (const float*)&wR[it];
            uint4 ahi, alo, whi;
            unsigned* ah = (unsigned*)&ahi; unsigned* al = (unsigned*)&alo;
            unsigned* wh = (unsigned*)&whi;
#pragma unroll
            for (int j = 0; j < 4; j++) {
                unsigned hh = f2tf32(av[j]);
                ah[j] = hh;
                al[j] = f2tf32(av[j] - __uint_as_float(hh));
                wh[j] = f2tf32(wv[j]);
            }
            *(uint4*)&sm.Ah[r][lk4] = ahi;
            *(uint4*)&sm.Al[r][lk4] = alo;
            *(uint4*)&sm.Wh[r][lk4] = whi;
        }
        __syncthreads();

        if (k0 + 16 < DMODEL) {
#pragma unroll
            for (int it = 0; it < 2; it++) {
                int r = lr + (it << 6);
                aR[it] = *(const float4*)&Ap[(m0 + r) * DMODEL + k0 + 16 + lk4];
                wR[it] = *(const float4*)&W[(n0 + r) * DMODEL + k0 + 16 + lk4];
            }
        }

#pragma unroll
        for (int ks = 0; ks < 2; ks++) {
            const int kk = (ks << 3) + tg;
            unsigned ah[2][4], al[2][4];
#pragma unroll
            for (int mf = 0; mf < 2; mf++) {
                int r0 = (wm << 5) + (mf << 4) + g;
                ah[mf][0] = sm.Ah[r0][kk];     ah[mf][1] = sm.Ah[r0 + 8][kk];
                ah[mf][2] = sm.Ah[r0][kk + 4]; ah[mf][3] = sm.Ah[r0 + 8][kk + 4];
                al[mf][0] = sm.Al[r0][kk];     al[mf][1] = sm.Al[r0 + 8][kk];
                al[mf][2] = sm.Al[r0][kk + 4]; al[mf][3] = sm.Al[r0 + 8][kk + 4];
            }
#pragma unroll
            for (int nf = 0; nf < 8; nf++) {
                int nr = (wn << 6) + (nf << 3) + g;
                unsigned bh[2];
                bh[0] = sm.Wh[nr][kk]; bh[1] = sm.Wh[nr][kk + 4];
#pragma unroll
                for (int mf = 0; mf < 2; mf++) {
                    mma_tf32(acc[mf][nf], al[mf], bh);   // lo*hi
                    mma_tf32(acc[mf][nf], ah[mf], bh);   // hi*hi
                }
            }
        }
    }
}

// ---- fused Q/K/V projections: blockIdx.z selects the GEMM.
// Outputs are rounded to tf32 so the attention kernel needs NO cvt. ----
__global__ __launch_bounds__(256, 2) void gemm_qkv_kernel(
    const float* __restrict__ query, const float* __restrict__ key,
    const float* __restrict__ value, const float* __restrict__ Wq,
    const float* __restrict__ Wk, const float* __restrict__ Wv)
{
    const int z = blockIdx.z;
    const float* Ap = (z == 0) ? query : ((z == 1) ? key : value);
    const float* W  = (z == 0) ? Wq    : ((z == 1) ? Wk  : Wv);
    float* outp     = (z == 0) ? g_Q   : ((z == 1) ? g_K : g_V);

    const int m0 = blockIdx.y << 7;
    const int n0 = blockIdx.x << 7;

    float acc[2][8][4];
    gemm_core(Ap, W, m0, n0, acc);

    const int tid  = threadIdx.x;
    const int warp = tid >> 5;
    const int lane = tid & 31;
    const int g    = lane >> 2;
    const int tg   = lane & 3;
    const int wm   = warp >> 1;
    const int wn   = warp & 1;

#pragma unroll
    for (int mf = 0; mf < 2; mf++) {
        int m = m0 + (wm << 5) + (mf << 4) + g;
        int bb0 = m >> 11;
        int s   = m & 2047;
        int mb1 = m + 8;
        int bb1 = mb1 >> 11;
        int s1  = mb1 & 2047;
#pragma unroll
        for (int nf = 0; nf < 8; nf++) {
            int n = n0 + (wn << 6) + (nf << 3) + (tg << 1);
            int h = n >> 6;
            int d = n & 63;
            float2 w0, w1;
            w0.x = __uint_as_float(f2tf32(acc[mf][nf][0]));
            w0.y = __uint_as_float(f2tf32(acc[mf][nf][1]));
            w1.x = __uint_as_float(f2tf32(acc[mf][nf][2]));
            w1.y = __uint_as_float(f2tf32(acc[mf][nf][3]));
            *(float2*)&outp[(((bb0 << 4) + h) * SEQ + s) * DK + d] = w0;
            *(float2*)&outp[(((bb1 << 4) + h) * SEQ + s1) * DK + d] = w1;
        }
    }
}

// ---- output projection: C = g_O @ Wout^T + bias ----
__global__ __launch_bounds__(256, 2) void gemm_out_kernel(
    const float* __restrict__ Wout, const float* __restrict__ bias,
    float* __restrict__ outFlat)
{
    const int m0 = blockIdx.y << 7;
    const int n0 = blockIdx.x << 7;

    float acc[2][8][4];
    gemm_core(g_O, Wout, m0, n0, acc);

    const int tid  = threadIdx.x;
    const int warp = tid >> 5;
    const int lane = tid & 31;
    const int g    = lane >> 2;
    const int tg   = lane & 3;
    const int wm   = warp >> 1;
    const int wn   = warp & 1;

#pragma unroll
    for (int mf = 0; mf < 2; mf++) {
        int r0 = m0 + (wm << 5) + (mf << 4) + g;
#pragma unroll
        for (int nf = 0; nf < 8; nf++) {
            int n = n0 + (wn << 6) + (nf << 3) + (tg << 1);
            float2 bi = *(const float2*)&bias[n];
            float2 w0, w1;
            w0.x = acc[mf][nf][0] + bi.x; w0.y = acc[mf][nf][1] + bi.y;
            w1.x = acc[mf][nf][2] + bi.x; w1.y = acc[mf][nf][3] + bi.y;
            *(float2*)&outFlat[r0 * DMODEL + n] = w0;
            *(float2*)&outFlat[(r0 + 8) * DMODEL + n] = w1;
        }
    }
}

// ---------------------------------------------------------------------------
// Flash attention, tf32 mma.sync, cp.async double-buffered K/V.
// g_Q/g_K/g_V hold tf32-rounded floats -> NO cvt needed in inner loops:
// smem words feed the MMA directly as bit patterns. (Unchanged from R5.)
// ---------------------------------------------------------------------------
#define AQP_ST 72
#define AK_ST  68
#define AV_ST  72
#define KBUF_W (64 * AK_ST)
#define VBUF_W (64 * AV_ST)
#define ATTN_SMEM_BYTES ((128 * AQP_ST + 2 * KBUF_W + 2 * VBUF_W) * 4)  // 108544

__global__ __launch_bounds__(256, 2) void attn_mma_kernel(
    const unsigned char* __restrict__ mask, const int* __restrict__ is_causal_p)
{
    extern __shared__ unsigned smu[];
    unsigned* QPs  = smu;                       // [128][72]
    unsigned* Kbuf = smu + 128 * AQP_ST;        // 2 x [64][68]
    unsigned* Vbuf = Kbuf + 2 * KBUF_W;         // 2 x [64][72]

    const int bh = blockIdx.y;
    const int qt = gridDim.x - 1 - blockIdx.x;  // heavy (large-ntiles) CTAs first
    const int b  = bh >> 4;
    const int h  = bh & 15;
    const int causal = is_causal_p[0];
    const int q0 = qt << 7;

    const int tid  = threadIdx.x;
    const int warp = tid >> 5;
    const int lane = tid & 31;
    const int g    = lane >> 2;
    const int tg   = lane & 3;

    const float* Qg = g_Q + ((size_t)bh * SEQ + q0) * DK;
    const float* Kg = g_K + (size_t)bh * SEQ * DK;
    const float* Vg = g_V + (size_t)bh * SEQ * DK;

    const int lrow = tid >> 4;              // 0..15
    const int lc4  = (tid & 15) << 2;       // 0,4,..,60

    // ---- Load Q tile (already tf32-valued): plain copy ----
#pragma unroll
    for (int it = 0; it < 8; it++) {
        int r = lrow + (it << 4);
        *(uint4*)&QPs[r * AQP_ST + lc4] = *(const uint4*)&Qg[r * DK + lc4];
    }

    // ---- cp.async tile 0 into buffer 0 ----
#pragma unroll
    for (int it = 0; it < 4; it++) {
        int r = lrow + (it << 4);
        unsigned kd = (unsigned)__cvta_generic_to_shared(&Kbuf[r * AK_ST + lc4]);
        CP_ASYNC16(kd, &Kg[r * DK + lc4]);
        unsigned vd = (unsigned)__cvta_generic_to_shared(&Vbuf[r * AV_ST + lc4]);
        CP_ASYNC16(vd, &Vg[r * DK + lc4]);
    }
    CP_COMMIT();
    __syncthreads();

    // ---- Q fragments ----
    const int r0 = (warp << 4) + g;
    const int r1 = r0 + 8;
    unsigned qf[8][4];
#pragma unroll
    for (int ks = 0; ks < 8; ks++) {
        int k = (ks << 3) + tg;
        qf[ks][0] = QPs[r0 * AQP_ST + k];
        qf[ks][1] = QPs[r1 * AQP_ST + k];
        qf[ks][2] = QPs[r0 * AQP_ST + k + 4];
        qf[ks][3] = QPs[r1 * AQP_ST + k + 4];
    }

    const int gr0 = q0 + r0;
    const int gr1 = q0 + r1;
    const unsigned char* mrow0 = mask + (size_t)b * SEQ * SEQ + (size_t)gr0 * SEQ;
    const unsigned char* mrow1 = mask + (size_t)b * SEQ * SEQ + (size_t)gr1 * SEQ;

    float m0 = -1e30f, m1 = -1e30f, l0 = 0.f, l1 = 0.f;
    float of[8][4];
#pragma unroll
    for (int nf = 0; nf < 8; nf++)
#pragma unroll
        for (int j = 0; j < 4; j++) of[nf][j] = 0.f;

    const int ntiles = causal ? (2 * qt + 2) : (SEQ / 64);
    const float scale = 0.125f;

    for (int t = 0; t < ntiles; t++) {
        const int k0 = t << 6;
        if (t > 0) __syncthreads();

        if (t + 1 < ntiles) {
            const int nb = (t + 1) & 1;
            const float* Kt = Kg + ((t + 1) << 6) * DK;
            const float* Vt = Vg + ((t + 1) << 6) * DK;
            unsigned* Kd = Kbuf + nb * KBUF_W;
            unsigned* Vd = Vbuf + nb * VBUF_W;
#pragma unroll
            for (int it = 0; it < 4; it++) {
                int r = lrow + (it << 4);
                unsigned kd = (unsigned)__cvta_generic_to_shared(&Kd[r * AK_ST + lc4]);
                CP_ASYNC16(kd, &Kt[r * DK + lc4]);
                unsigned vd = (unsigned)__cvta_generic_to_shared(&Vd[r * AV_ST + lc4]);
                CP_ASYNC16(vd, &Vt[r * DK + lc4]);
            }
        }
        CP_COMMIT();
        CP_WAIT1();
        __syncthreads();

        const unsigned* Kb = Kbuf + (t & 1) * KBUF_W;
        const unsigned* Vb = Vbuf + (t & 1) * VBUF_W;

        // ---- mask prefetch ----
        uchar2 mA[8], mB[8];
#pragma unroll
        for (int nf = 0; nf < 8; nf++) {
            int col = k0 + (nf << 3) + (tg << 1);
            mA[nf] = *(const uchar2*)(mrow0 + col);
            mB[nf] = *(const uchar2*)(mrow1 + col);
        }

        // ---- S = Q @ K^T (no cvt: bits already tf32) ----
        float s[8][4];
#pragma unroll
        for (int nf = 0; nf < 8; nf++)
#pragma unroll
            for (int j = 0; j < 4; j++) s[nf][j] = 0.f;

#pragma unroll
        for (int nf = 0; nf < 8; nf++) {
            int nrow = (nf << 3) + g;
#pragma unroll
            for (int ks = 0; ks < 8; ks++) {
                int k = (ks << 3) + tg;
                unsigned bb[2];
                bb[0] = Kb[nrow * AK_ST + k];
                bb[1] = Kb[nrow * AK_ST + k + 4];
                mma_tf32(s[nf], qf[ks], bb);
            }
        }

        // ---- scale + mask ----
#pragma unroll
        for (int nf = 0; nf < 8; nf++) {
            int col = k0 + (nf << 3) + (tg << 1);
            bool d00 = mA[nf].x || (causal && (col     > gr0));
            bool d01 = mA[nf].y || (causal && (col + 1 > gr0));
            bool d10 = mB[nf].x || (causal && (col     > gr1));
            bool d11 = mB[nf].y || (causal && (col + 1 > gr1));
            s[nf][0] = d00 ? -1e30f : s[nf][0] * scale;
            s[nf][1] = d01 ? -1e30f : s[nf][1] * scale;
            s[nf][2] = d10 ? -1e30f : s[nf][2] * scale;
            s[nf][3] = d11 ? -1e30f : s[nf][3] * scale;
        }

        // ---- online softmax ----
        float mx0 = -1e30f, mx1 = -1e30f;
#pragma unroll
        for (int nf = 0; nf < 8; nf++) {
            mx0 = fmaxf(mx0, fmaxf(s[nf][0], s[nf][1]));
            mx1 = fmaxf(mx1, fmaxf(s[nf][2], s[nf][3]));
        }
        mx0 = fmaxf(mx0, __shfl_xor_sync(0xffffffffu, mx0, 1));
        mx0 = fmaxf(mx0, __shfl_xor_sync(0xffffffffu, mx0, 2));
        mx1 = fmaxf(mx1, __shfl_xor_sync(0xffffffffu, mx1, 1));
        mx1 = fmaxf(mx1, __shfl_xor_sync(0xffffffffu, mx1, 2));
        float m0n = fmaxf(m0, mx0);
        float m1n = fmaxf(m1, mx1);
        float sf0 = __expf(m0 - m0n);
        float sf1 = __expf(m1 - m1n);
        float rs0 = 0.f, rs1 = 0.f;
#pragma unroll
        for (int nf = 0; nf < 8; nf++) {
            float p0 = __expf(s[nf][0] - m0n);
            float p1 = __expf(s[nf][1] - m0n);
            float p2 = __expf(s[nf][2] - m1n);
            float p3 = __expf(s[nf][3] - m1n);
            s[nf][0] = p0; s[nf][1] = p1; s[nf][2] = p2; s[nf][3] = p3;
            rs0 += p0 + p1;
            rs1 += p2 + p3;
        }
        rs0 += __shfl_xor_sync(0xffffffffu, rs0, 1);
        rs0 += __shfl_xor_sync(0xffffffffu, rs0, 2);
        rs1 += __shfl_xor_sync(0xffffffffu, rs1, 1);
        rs1 += __shfl_xor_sync(0xffffffffu, rs1, 2);
        l0 = l0 * sf0 + rs0;
        l1 = l1 * sf1 + rs1;
        m0 = m0n; m1 = m1n;
#pragma unroll
        for (int nf = 0; nf < 8; nf++) {
            of[nf][0] *= sf0; of[nf][1] *= sf0;
            of[nf][2] *= sf1; of[nf][3] *= sf1;
        }

        // ---- write P (tf32) to warp-local rows of QPs ----
#pragma unroll
        for (int nf = 0; nf < 8; nf++) {
            int c = (nf << 3) + (tg << 1);
            uint2 p0; p0.x = f2tf32(s[nf][0]); p0.y = f2tf32(s[nf][1]);
            uint2 p1; p1.x = f2tf32(s[nf][2]); p1.y = f2tf32(s[nf][3]);
            *(uint2*)&QPs[r0 * AQP_ST + c] = p0;
            *(uint2*)&QPs[r1 * AQP_ST + c] = p1;
        }
        __syncwarp();

        // ---- O += P @ V ----
#pragma unroll
        for (int ks = 0; ks < 8; ks++) {
            unsigned a[4];
            int k = (ks << 3) + tg;
            a[0] = QPs[r0 * AQP_ST + k];
            a[1] = QPs[r1 * AQP_ST + k];
            a[2] = QPs[r0 * AQP_ST + k + 4];
            a[3] = QPs[r1 * AQP_ST + k + 4];
#pragma unroll
            for (int nf = 0; nf < 8; nf++) {
                int n = (nf << 3) + g;
                unsigned bb[2];
                bb[0] = Vb[((ks << 3) + tg) * AV_ST + n];
                bb[1] = Vb[((ks << 3) + tg + 4) * AV_ST + n];
                mma_tf32(of[nf], a, bb);
            }
        }
        __syncwarp();
    }

    // ---- epilogue ----
    float inv0 = (m0 > -1e29f && l0 > 0.f) ? (1.f / l0) : 0.f;
    float inv1 = (m1 > -1e29f && l1 > 0.f) ? (1.f / l1) : 0.f;
    float* Og0 = g_O + ((size_t)b * SEQ + gr0) * DMODEL + (h << 6);
    float* Og1 = g_O + ((size_t)b * SEQ + gr1) * DMODEL + (h << 6);
#pragma unroll
    for (int nf = 0; nf < 8; nf++) {
        int c = (nf << 3) + (tg << 1);
        float2 w0; w0.x = of[nf][0] * inv0; w0.y = of[nf][1] * inv0;
        float2 w1; w1.x = of[nf][2] * inv1; w1.y = of[nf][3] * inv1;
        *(float2*)&Og0[c] = w0;
        *(float2*)&Og1[c] = w1;
    }
}

// ---------------------------------------------------------------------------
extern "C" void kernel_launch(void* const* d_in, const int* in_sizes, int n_in,
                              void* d_out, int out_size)
{
    const float* query = (const float*)d_in[0];
    const float* key   = (const float*)d_in[1];
    const float* value = (const float*)d_in[2];
    const unsigned char* mask = (const unsigned char*)d_in[3];
    const float* Wq    = (const float*)d_in[4];
    const float* Wk    = (const float*)d_in[5];
    const float* Wv    = (const float*)d_in[6];
    const float* Wout  = (const float*)d_in[7];
    const float* b_out = (const float*)d_in[8];
    const int* is_causal = (const int*)d_in[9];
    float* out = (float*)d_out;

    cudaFuncSetAttribute(attn_mma_kernel,
                         cudaFuncAttributeMaxDynamicSharedMemorySize, ATTN_SMEM_BYTES);

    dim3 qkvgrid(DMODEL / 128, MROWS / 128, 3);   // (8, 32, 3)
    gemm_qkv_kernel<<<qkvgrid, 256>>>(query, key, value, Wq, Wk, Wv);

    dim3 agrid(SEQ / 128, BATCH * NHEAD);         // (16, 32)
    attn_mma_kernel<<<agrid, 256, ATTN_SMEM_BYTES>>>(mask, is_causal);

    dim3 ogrid(DMODEL / 128, MROWS / 128);        // (8, 32)
    gemm_out_kernel<<<ogrid, 256>>>(Wout, b_out, out);
}